// round 1
// baseline (speedup 1.0000x reference)
#include <cuda_runtime.h>
#include <cuda_bf16.h>
#include <math.h>

// ---------------- problem constants (fixed by the dataset) ----------------
#define NN   50000          // nodes
#define EE   800000         // directed edges (before self loops)
#define EP   (EE + NN)      // edges + self loops = 850000
#define FF   128            // input features == H*C
#define HH   2              // heads
#define CC   64             // per-head channels
#define HC   128            // H*C
#define GG   128            // graphs
#define L1S  256
#define L2S  128
#define OUTS 10
#define NEG_SLOPE 0.2f

// ---------------- static device scratch (no allocations allowed) ----------
__device__ int   g_is64;
__device__ int   g_src[EP];
__device__ int   g_dst[EP];
__device__ int   g_bat[NN];
__device__ float g_in  [NN * HC];   // layer input (after bias+relu)
__device__ float g_h   [NN * HC];   // h = in @ W
__device__ float g_acc [NN * HC];   // aggregation accumulator
__device__ float g_as  [NN * HH];   // alpha_src per node
__device__ float g_ad  [NN * HH];   // alpha_dst per node
__device__ unsigned g_m[NN * HH];   // segment max (ordered-uint encoded)
__device__ float g_sum [NN * HH];   // segment sum of exp
__device__ float g_e   [EP * HH];   // per-edge logits / exp values
__device__ float g_pool[GG * HC];
__device__ float g_cnt [GG];
__device__ float g_g1  [GG * L1S];
__device__ float g_g2  [GG * L2S];

// ---------------- helpers ----------------
__device__ __forceinline__ unsigned enc_f(float x) {
    unsigned b = __float_as_uint(x);
    return (b & 0x80000000u) ? ~b : (b | 0x80000000u);
}
__device__ __forceinline__ float dec_f(unsigned u) {
    return (u & 0x80000000u) ? __uint_as_float(u ^ 0x80000000u)
                             : __uint_as_float(~u);
}
__device__ __forceinline__ float lrelu(float v) {
    return v > 0.f ? v : NEG_SLOPE * v;
}

// ---------------- dtype sniffing + index conversion ----------------
__global__ void k_detect(const void* edge) {
    if (threadIdx.x == 0 && blockIdx.x == 0) {
        const unsigned long long* q = (const unsigned long long*)edge;
        int is64 = 1;
        for (int i = 0; i < 1024; i++) {
            if (q[i] >> 32) { is64 = 0; break; }
        }
        g_is64 = is64;
    }
}

__global__ void k_conv_edges(const void* edge) {
    int i = blockIdx.x * blockDim.x + threadIdx.x;
    if (i >= EP) return;
    if (i < EE) {
        int s, d;
        if (g_is64) {
            const long long* p = (const long long*)edge;
            s = (int)p[i]; d = (int)p[EE + i];
        } else {
            const int* p = (const int*)edge;
            s = p[i]; d = p[EE + i];
        }
        g_src[i] = s; g_dst[i] = d;
    } else {               // self loops
        g_src[i] = i - EE; g_dst[i] = i - EE;
    }
}

__global__ void k_conv_batch(const void* batch) {
    int i = blockIdx.x * blockDim.x + threadIdx.x;
    if (i >= NN) return;
    if (g_is64) g_bat[i] = (int)((const long long*)batch)[i];
    else        g_bat[i] = ((const int*)batch)[i];
}

// ---------------- GEMM: h[M,128] = A[M,128] @ W[128,128] ----------------
// use_x: A comes from the x argument; else from g_in
__global__ void k_gemm(const float* __restrict__ A,
                       const float* __restrict__ W, int use_x) {
    const int BM = 64, BK = 32;
    __shared__ float As[BM][BK];
    __shared__ float Bs[BK][HC];
    const float* Ap = use_x ? A : (const float*)g_in;

    int row0 = blockIdx.x * BM;
    int tid = threadIdx.x;                     // 256 threads
    int tcol = (tid & 31) * 4;                 // 4 cols
    int trow = (tid >> 5) * 8;                 // 8 rows
    float acc[8][4];
#pragma unroll
    for (int i = 0; i < 8; i++)
#pragma unroll
        for (int j = 0; j < 4; j++) acc[i][j] = 0.f;

    for (int k0 = 0; k0 < HC; k0 += BK) {
        for (int i = tid; i < BM * BK; i += 256) {
            int r = i / BK, c = i % BK;
            int gr = row0 + r;
            As[r][c] = (gr < NN) ? Ap[gr * HC + k0 + c] : 0.f;
        }
        for (int i = tid; i < BK * HC; i += 256) {
            int r = i / HC, c = i % HC;
            Bs[r][c] = W[(k0 + r) * HC + c];
        }
        __syncthreads();
#pragma unroll
        for (int k = 0; k < BK; k++) {
            float bv[4];
#pragma unroll
            for (int j = 0; j < 4; j++) bv[j] = Bs[k][tcol + j];
#pragma unroll
            for (int i = 0; i < 8; i++) {
                float av = As[trow + i][k];
#pragma unroll
                for (int j = 0; j < 4; j++) acc[i][j] += av * bv[j];
            }
        }
        __syncthreads();
    }
    for (int i = 0; i < 8; i++) {
        int gr = row0 + trow + i;
        if (gr < NN) {
#pragma unroll
            for (int j = 0; j < 4; j++) g_h[gr * HC + tcol + j] = acc[i][j];
        }
    }
}

// ---------------- alpha_s / alpha_d: warp per node ----------------
__global__ void k_alpha(const float* __restrict__ a_src,
                        const float* __restrict__ a_dst) {
    int warp = (blockIdx.x * blockDim.x + threadIdx.x) >> 5;
    int lane = threadIdx.x & 31;
    if (warp >= NN) return;
    int f = lane * 4;                 // 4 features per lane
    int head = f >> 6;                // lanes 0-15 head0, 16-31 head1
    const float4 hv = *(const float4*)&g_h[warp * HC + f];
    const float4 sv = *(const float4*)&a_src[f];
    const float4 dv = *(const float4*)&a_dst[f];
    float ps = hv.x * sv.x + hv.y * sv.y + hv.z * sv.z + hv.w * sv.w;
    float pd = hv.x * dv.x + hv.y * dv.y + hv.z * dv.z + hv.w * dv.w;
#pragma unroll
    for (int o = 1; o < 16; o <<= 1) {
        ps += __shfl_xor_sync(0xFFFFFFFFu, ps, o);
        pd += __shfl_xor_sync(0xFFFFFFFFu, pd, o);
    }
    if ((lane & 15) == 0) {
        g_as[warp * HH + head] = ps;
        g_ad[warp * HH + head] = pd;
    }
}

// ---------------- zero per-layer scratch ----------------
__global__ void k_zero_layer() {
    int i = blockIdx.x * blockDim.x + threadIdx.x;
    if (i < NN * HC) g_acc[i] = 0.f;
    if (i < NN * HH) { g_m[i] = 0u; g_sum[i] = 0.f; }
}

// ---------------- edge pass A: logits + segment max ----------------
__global__ void k_edgeA() {
    int i = blockIdx.x * blockDim.x + threadIdx.x;
    if (i >= EP) return;
    int s = g_src[i], d = g_dst[i];
#pragma unroll
    for (int h = 0; h < HH; h++) {
        float e = lrelu(g_as[s * HH + h] + g_ad[d * HH + h]);
        g_e[i * HH + h] = e;
        atomicMax(&g_m[d * HH + h], enc_f(e));
    }
}

// ---------------- edge pass B: exp + segment sum ----------------
__global__ void k_edgeB() {
    int i = blockIdx.x * blockDim.x + threadIdx.x;
    if (i >= EP) return;
    int d = g_dst[i];
#pragma unroll
    for (int h = 0; h < HH; h++) {
        float m = dec_f(g_m[d * HH + h]);
        float ex = expf(g_e[i * HH + h] - m);
        g_e[i * HH + h] = ex;
        atomicAdd(&g_sum[d * HH + h], ex);
    }
}

// ---------------- edge pass C: weighted message aggregation ----------------
// 2 edges per 256-thread block; thread handles one feature
__global__ void k_edgeC() {
    int tid = threadIdx.x;
    int eid = blockIdx.x * 2 + (tid >> 7);
    if (eid >= EP) return;
    int f = tid & 127;
    int head = f >> 6;
    int s = g_src[eid], d = g_dst[eid];
    float a = g_e[eid * HH + head] / (g_sum[d * HH + head] + 1e-16f);
    float v = g_h[s * HC + f] * a;
    atomicAdd(&g_acc[d * HC + f], v);
}

// ---------------- bias + relu into next-layer input ----------------
__global__ void k_bias_relu(const float* __restrict__ b) {
    int i = blockIdx.x * blockDim.x + threadIdx.x;
    if (i >= NN * HC) return;
    float v = g_acc[i] + b[i & 127];
    g_in[i] = v > 0.f ? v : 0.f;
}

// ---------------- pooling ----------------
__global__ void k_zero_pool() {
    int i = blockIdx.x * blockDim.x + threadIdx.x;
    if (i < GG * HC) g_pool[i] = 0.f;
    if (i < GG) g_cnt[i] = 0.f;
}
__global__ void k_count() {
    int i = blockIdx.x * blockDim.x + threadIdx.x;
    if (i >= NN) return;
    atomicAdd(&g_cnt[g_bat[i]], 1.f);
}
__global__ void k_pool() {
    int i = blockIdx.x * blockDim.x + threadIdx.x;
    if (i >= NN * HC) return;
    int n = i >> 7, f = i & 127;
    atomicAdd(&g_pool[g_bat[n] * HC + f], g_in[n * HC + f]);
}

// ---------------- MLP ----------------
__global__ void k_mlp1(const float* __restrict__ w, const float* __restrict__ b) {
    __shared__ float row[HC];
    int g = blockIdx.x, col = threadIdx.x;      // 256 threads
    if (col < HC) {
        float c = g_cnt[g];
        row[col] = g_pool[g * HC + col] / fmaxf(c, 1.f);
    }
    __syncthreads();
    float acc = 0.f;
#pragma unroll 4
    for (int k = 0; k < HC; k++) acc += row[k] * w[k * L1S + col];
    acc += b[col];
    g_g1[g * L1S + col] = acc > 0.f ? acc : 0.f;
}
__global__ void k_mlp2(const float* __restrict__ w, const float* __restrict__ b) {
    __shared__ float row[L1S];
    int g = blockIdx.x, tid = threadIdx.x;      // 256 threads
    row[tid] = g_g1[g * L1S + tid];
    __syncthreads();
    if (tid < L2S) {
        float acc = 0.f;
#pragma unroll 4
        for (int k = 0; k < L1S; k++) acc += row[k] * w[k * L2S + tid];
        acc += b[tid];
        g_g2[g * L2S + tid] = acc > 0.f ? acc : 0.f;
    }
}
__global__ void k_mlp3(const float* __restrict__ w, const float* __restrict__ b,
                       float* __restrict__ out) {
    __shared__ float row[L2S];
    int g = blockIdx.x, tid = threadIdx.x;      // 128 threads
    row[tid] = g_g2[g * L2S + tid];
    __syncthreads();
    if (tid < OUTS) {
        float acc = 0.f;
#pragma unroll 4
        for (int k = 0; k < L2S; k++) acc += row[k] * w[k * OUTS + tid];
        out[g * OUTS + tid] = acc + b[tid];
    }
}

// ---------------- host orchestration ----------------
extern "C" void kernel_launch(void* const* d_in, const int* in_sizes, int n_in,
                              void* d_out, int out_size) {
    const float* x       = (const float*)d_in[0];
    const void*  edge    = d_in[1];
    const void*  batch   = d_in[2];
    const float* W[3]    = {(const float*)d_in[3], (const float*)d_in[7],  (const float*)d_in[11]};
    const float* asrc[3] = {(const float*)d_in[4], (const float*)d_in[8],  (const float*)d_in[12]};
    const float* adst[3] = {(const float*)d_in[5], (const float*)d_in[9],  (const float*)d_in[13]};
    const float* bias[3] = {(const float*)d_in[6], (const float*)d_in[10], (const float*)d_in[14]};
    const float* lin1_w = (const float*)d_in[15];
    const float* lin1_b = (const float*)d_in[16];
    const float* lin2_w = (const float*)d_in[17];
    const float* lin2_b = (const float*)d_in[18];
    const float* out_w  = (const float*)d_in[19];
    const float* out_b  = (const float*)d_in[20];
    float* out = (float*)d_out;

    k_detect<<<1, 32>>>(edge);
    k_conv_edges<<<(EP + 255) / 256, 256>>>(edge);
    k_conv_batch<<<(NN + 255) / 256, 256>>>(batch);

    const int gemm_blocks  = (NN + 63) / 64;
    const int nf_blocks    = (NN * HC + 255) / 256;
    const int edge_blocks  = (EP + 255) / 256;
    const int alpha_blocks = (NN + 7) / 8;          // 8 warps per block

    for (int l = 0; l < 3; l++) {
        k_gemm<<<gemm_blocks, 256>>>(x, W[l], l == 0 ? 1 : 0);
        k_alpha<<<alpha_blocks, 256>>>(asrc[l], adst[l]);
        k_zero_layer<<<nf_blocks, 256>>>();
        k_edgeA<<<edge_blocks, 256>>>();
        k_edgeB<<<edge_blocks, 256>>>();
        k_edgeC<<<(EP + 1) / 2, 256>>>();
        k_bias_relu<<<nf_blocks, 256>>>(bias[l]);
    }

    k_zero_pool<<<(GG * HC + 255) / 256, 256>>>();
    k_count<<<(NN + 255) / 256, 256>>>();
    k_pool<<<nf_blocks, 256>>>();
    k_mlp1<<<GG, L1S>>>(lin1_w, lin1_b);
    k_mlp2<<<GG, 256>>>(lin2_w, lin2_b);
    k_mlp3<<<GG, L2S>>>(out_w, out_b, out);
}

// round 2
// speedup vs baseline: 2.9282x; 2.9282x over previous
#include <cuda_runtime.h>
#include <cuda_bf16.h>
#include <math.h>

// ---------------- problem constants ----------------
#define NN   50000
#define EE   800000
#define EP   (EE + NN)      // 850000
#define HH   2
#define HC   128
#define GG   128
#define L1S  256
#define L2S  128
#define OUTS 10
#define NEG_SLOPE 0.2f

// ---------------- static device scratch ----------------
__device__ int   g_is64;
__device__ int   g_src[EP];
__device__ int   g_dst[EP];
__device__ int   g_bat[NN];
__device__ int   g_deg[NN];
__device__ int   g_fill[NN];
__device__ int   g_ptr[NN + 1];
__device__ int   g_col[EP];
__device__ float g_in  [NN * HC];
__device__ float g_h   [NN * HC];
__device__ float g_as  [NN * HH];
__device__ float g_ad  [NN * HH];
__device__ float g_e   [EP * HH];
__device__ float g_pool[GG * HC];
__device__ float g_cnt [GG];
__device__ float g_g1  [GG * L1S];
__device__ float g_g2  [GG * L2S];

__device__ __forceinline__ float lrelu(float v) {
    return v > 0.f ? v : NEG_SLOPE * v;
}

// ---------------- dtype sniffing + index conversion + degree histogram ----
__global__ void k_detect(const void* edge) {
    if (threadIdx.x == 0 && blockIdx.x == 0) {
        const unsigned long long* q = (const unsigned long long*)edge;
        int is64 = 1;
        for (int i = 0; i < 1024; i++) {
            if (q[i] >> 32) { is64 = 0; break; }
        }
        g_is64 = is64;
    }
}

__global__ void k_zero_deg() {
    int i = blockIdx.x * blockDim.x + threadIdx.x;
    if (i < NN) g_deg[i] = 0;
}

__global__ void k_conv_edges(const void* edge) {
    int i = blockIdx.x * blockDim.x + threadIdx.x;
    if (i >= EP) return;
    int s, d;
    if (i < EE) {
        if (g_is64) {
            const long long* p = (const long long*)edge;
            s = (int)p[i]; d = (int)p[EE + i];
        } else {
            const int* p = (const int*)edge;
            s = p[i]; d = p[EE + i];
        }
    } else {
        s = i - EE; d = i - EE;
    }
    g_src[i] = s; g_dst[i] = d;
    atomicAdd(&g_deg[d], 1);
}

__global__ void k_conv_batch(const void* batch) {
    int i = blockIdx.x * blockDim.x + threadIdx.x;
    if (i >= NN) return;
    if (g_is64) g_bat[i] = (int)((const long long*)batch)[i];
    else        g_bat[i] = ((const int*)batch)[i];
}

// ---------------- single-block exclusive scan over 50000 degrees ----------
#define SCAN_T 1024
#define SCAN_CH 49          // 1024*49 = 50176 >= NN
__global__ void k_scan() {
    __shared__ int sh[SCAN_T];
    int t = threadIdx.x;
    int base = t * SCAN_CH;
    int local[SCAN_CH];
    int sum = 0;
#pragma unroll
    for (int i = 0; i < SCAN_CH; i++) {
        int idx = base + i;
        int v = (idx < NN) ? g_deg[idx] : 0;
        local[i] = sum;
        sum += v;
    }
    sh[t] = sum;
    __syncthreads();
    for (int o = 1; o < SCAN_T; o <<= 1) {
        int v = 0;
        if (t >= o) v = sh[t - o];
        __syncthreads();
        if (t >= o) sh[t] += v;
        __syncthreads();
    }
    int off = (t > 0) ? sh[t - 1] : 0;
#pragma unroll
    for (int i = 0; i < SCAN_CH; i++) {
        int idx = base + i;
        if (idx < NN) { g_ptr[idx] = off + local[i]; g_fill[idx] = 0; }
    }
    if (t == SCAN_T - 1) g_ptr[NN] = sh[SCAN_T - 1];
}

__global__ void k_scatter() {
    int i = blockIdx.x * blockDim.x + threadIdx.x;
    if (i >= EP) return;
    int d = g_dst[i];
    int pos = atomicAdd(&g_fill[d], 1);
    g_col[g_ptr[d] + pos] = g_src[i];
}

// ---------------- GEMM: h[M,128] = A[M,128] @ W[128,128] ----------------
__global__ void k_gemm(const float* __restrict__ A,
                       const float* __restrict__ W, int use_x) {
    const int BM = 64, BK = 32;
    __shared__ float As[BM][BK];
    __shared__ float Bs[BK][HC];
    const float* Ap = use_x ? A : (const float*)g_in;

    int row0 = blockIdx.x * BM;
    int tid = threadIdx.x;
    int tcol = (tid & 31) * 4;
    int trow = (tid >> 5) * 8;
    float acc[8][4];
#pragma unroll
    for (int i = 0; i < 8; i++)
#pragma unroll
        for (int j = 0; j < 4; j++) acc[i][j] = 0.f;

    for (int k0 = 0; k0 < HC; k0 += BK) {
        for (int i = tid; i < BM * BK; i += 256) {
            int r = i / BK, c = i % BK;
            int gr = row0 + r;
            As[r][c] = (gr < NN) ? Ap[gr * HC + k0 + c] : 0.f;
        }
        for (int i = tid; i < BK * HC; i += 256) {
            int r = i / HC, c = i % HC;
            Bs[r][c] = W[(k0 + r) * HC + c];
        }
        __syncthreads();
#pragma unroll
        for (int k = 0; k < BK; k++) {
            float bv[4];
#pragma unroll
            for (int j = 0; j < 4; j++) bv[j] = Bs[k][tcol + j];
#pragma unroll
            for (int i = 0; i < 8; i++) {
                float av = As[trow + i][k];
#pragma unroll
                for (int j = 0; j < 4; j++) acc[i][j] += av * bv[j];
            }
        }
        __syncthreads();
    }
    for (int i = 0; i < 8; i++) {
        int gr = row0 + trow + i;
        if (gr < NN) {
#pragma unroll
            for (int j = 0; j < 4; j++) g_h[gr * HC + tcol + j] = acc[i][j];
        }
    }
}

// ---------------- alpha_s / alpha_d: warp per node ----------------
__global__ void k_alpha(const float* __restrict__ a_src,
                        const float* __restrict__ a_dst) {
    int warp = (blockIdx.x * blockDim.x + threadIdx.x) >> 5;
    int lane = threadIdx.x & 31;
    if (warp >= NN) return;
    int f = lane * 4;
    int head = f >> 6;
    const float4 hv = *(const float4*)&g_h[warp * HC + f];
    const float4 sv = *(const float4*)&a_src[f];
    const float4 dv = *(const float4*)&a_dst[f];
    float ps = hv.x * sv.x + hv.y * sv.y + hv.z * sv.z + hv.w * sv.w;
    float pd = hv.x * dv.x + hv.y * dv.y + hv.z * dv.z + hv.w * dv.w;
#pragma unroll
    for (int o = 1; o < 16; o <<= 1) {
        ps += __shfl_xor_sync(0xFFFFFFFFu, ps, o);
        pd += __shfl_xor_sync(0xFFFFFFFFu, pd, o);
    }
    if ((lane & 15) == 0) {
        g_as[warp * HH + head] = ps;
        g_ad[warp * HH + head] = pd;
    }
}

// ---------------- fused softmax + aggregation: warp per dst node ---------
__global__ void __launch_bounds__(256) k_node(const float* __restrict__ b) {
    int w = (blockIdx.x * blockDim.x + threadIdx.x) >> 5;
    if (w >= NN) return;
    int lane = threadIdx.x & 31;
    int beg = g_ptr[w], end = g_ptr[w + 1];
    float2 ad = *(const float2*)&g_ad[w * 2];

    // pass 1a: raw logits + warp max
    float m0 = -INFINITY, m1 = -INFINITY;
    for (int j = beg + lane; j < end; j += 32) {
        int s = g_col[j];
        float2 as = *(const float2*)&g_as[s * 2];
        float e0 = lrelu(as.x + ad.x);
        float e1 = lrelu(as.y + ad.y);
        *(float2*)&g_e[j * 2] = make_float2(e0, e1);
        m0 = fmaxf(m0, e0); m1 = fmaxf(m1, e1);
    }
#pragma unroll
    for (int o = 16; o; o >>= 1) {
        m0 = fmaxf(m0, __shfl_xor_sync(0xFFFFFFFFu, m0, o));
        m1 = fmaxf(m1, __shfl_xor_sync(0xFFFFFFFFu, m1, o));
    }

    // pass 1b: exp + warp sum (each lane re-reads its own writes)
    float s0 = 0.f, s1 = 0.f;
    for (int j = beg + lane; j < end; j += 32) {
        float2 e = *(const float2*)&g_e[j * 2];
        float x0 = __expf(e.x - m0);
        float x1 = __expf(e.y - m1);
        *(float2*)&g_e[j * 2] = make_float2(x0, x1);
        s0 += x0; s1 += x1;
    }
#pragma unroll
    for (int o = 16; o; o >>= 1) {
        s0 += __shfl_xor_sync(0xFFFFFFFFu, s0, o);
        s1 += __shfl_xor_sync(0xFFFFFFFFu, s1, o);
    }
    float inv0 = 1.f / (s0 + 1e-16f);
    float inv1 = 1.f / (s1 + 1e-16f);
    __syncwarp();   // make all lanes' g_e writes visible warp-wide

    // pass 2: gather-accumulate 4 features per lane
    int f = lane * 4;
    int head = f >> 6;
    float inv = head ? inv1 : inv0;
    float4 acc = make_float4(0.f, 0.f, 0.f, 0.f);
    int j = beg;
    for (; j + 1 < end; j += 2) {
        int s0i = g_col[j];
        int s1i = g_col[j + 1];
        float a0 = g_e[j * 2 + head] * inv;
        float a1 = g_e[(j + 1) * 2 + head] * inv;
        float4 h0 = *(const float4*)&g_h[s0i * HC + f];
        float4 h1 = *(const float4*)&g_h[s1i * HC + f];
        acc.x += a0 * h0.x + a1 * h1.x;
        acc.y += a0 * h0.y + a1 * h1.y;
        acc.z += a0 * h0.z + a1 * h1.z;
        acc.w += a0 * h0.w + a1 * h1.w;
    }
    if (j < end) {
        int s = g_col[j];
        float a = g_e[j * 2 + head] * inv;
        float4 hv = *(const float4*)&g_h[s * HC + f];
        acc.x += a * hv.x; acc.y += a * hv.y;
        acc.z += a * hv.z; acc.w += a * hv.w;
    }

    // epilogue: bias + relu
    float4 bb = *(const float4*)&b[f];
    acc.x = fmaxf(acc.x + bb.x, 0.f);
    acc.y = fmaxf(acc.y + bb.y, 0.f);
    acc.z = fmaxf(acc.z + bb.z, 0.f);
    acc.w = fmaxf(acc.w + bb.w, 0.f);
    *(float4*)&g_in[w * HC + f] = acc;
}

// ---------------- pooling ----------------
__global__ void k_zero_pool() {
    int i = blockIdx.x * blockDim.x + threadIdx.x;
    if (i < GG * HC) g_pool[i] = 0.f;
    if (i < GG) g_cnt[i] = 0.f;
}
__global__ void k_count() {
    int i = blockIdx.x * blockDim.x + threadIdx.x;
    if (i >= NN) return;
    atomicAdd(&g_cnt[g_bat[i]], 1.f);
}
__global__ void k_pool() {
    int i = blockIdx.x * blockDim.x + threadIdx.x;
    if (i >= NN * HC) return;
    int n = i >> 7, f = i & 127;
    atomicAdd(&g_pool[g_bat[n] * HC + f], g_in[n * HC + f]);
}

// ---------------- MLP ----------------
__global__ void k_mlp1(const float* __restrict__ w, const float* __restrict__ b) {
    __shared__ float row[HC];
    int g = blockIdx.x, col = threadIdx.x;
    if (col < HC) {
        float c = g_cnt[g];
        row[col] = g_pool[g * HC + col] / fmaxf(c, 1.f);
    }
    __syncthreads();
    float acc = 0.f;
#pragma unroll 4
    for (int k = 0; k < HC; k++) acc += row[k] * w[k * L1S + col];
    acc += b[col];
    g_g1[g * L1S + col] = acc > 0.f ? acc : 0.f;
}
__global__ void k_mlp2(const float* __restrict__ w, const float* __restrict__ b) {
    __shared__ float row[L1S];
    int g = blockIdx.x, tid = threadIdx.x;
    row[tid] = g_g1[g * L1S + tid];
    __syncthreads();
    if (tid < L2S) {
        float acc = 0.f;
#pragma unroll 4
        for (int k = 0; k < L1S; k++) acc += row[k] * w[k * L2S + tid];
        acc += b[tid];
        g_g2[g * L2S + tid] = acc > 0.f ? acc : 0.f;
    }
}
__global__ void k_mlp3(const float* __restrict__ w, const float* __restrict__ b,
                       float* __restrict__ out) {
    __shared__ float row[L2S];
    int g = blockIdx.x, tid = threadIdx.x;
    row[tid] = g_g2[g * L2S + tid];
    __syncthreads();
    if (tid < OUTS) {
        float acc = 0.f;
#pragma unroll 4
        for (int k = 0; k < L2S; k++) acc += row[k] * w[k * OUTS + tid];
        out[g * OUTS + tid] = acc + b[tid];
    }
}

// ---------------- host orchestration ----------------
extern "C" void kernel_launch(void* const* d_in, const int* in_sizes, int n_in,
                              void* d_out, int out_size) {
    const float* x       = (const float*)d_in[0];
    const void*  edge    = d_in[1];
    const void*  batch   = d_in[2];
    const float* W[3]    = {(const float*)d_in[3], (const float*)d_in[7],  (const float*)d_in[11]};
    const float* asrc[3] = {(const float*)d_in[4], (const float*)d_in[8],  (const float*)d_in[12]};
    const float* adst[3] = {(const float*)d_in[5], (const float*)d_in[9],  (const float*)d_in[13]};
    const float* bias[3] = {(const float*)d_in[6], (const float*)d_in[10], (const float*)d_in[14]};
    const float* lin1_w = (const float*)d_in[15];
    const float* lin1_b = (const float*)d_in[16];
    const float* lin2_w = (const float*)d_in[17];
    const float* lin2_b = (const float*)d_in[18];
    const float* out_w  = (const float*)d_in[19];
    const float* out_b  = (const float*)d_in[20];
    float* out = (float*)d_out;

    const int edge_blocks  = (EP + 255) / 256;
    const int node_blocks  = (NN + 255) / 256;
    const int gemm_blocks  = (NN + 63) / 64;
    const int nf_blocks    = (NN * HC + 255) / 256;
    const int warp8_blocks = (NN + 7) / 8;

    // CSR build (once per launch)
    k_detect<<<1, 32>>>(edge);
    k_zero_deg<<<node_blocks, 256>>>();
    k_conv_edges<<<edge_blocks, 256>>>(edge);
    k_conv_batch<<<node_blocks, 256>>>(batch);
    k_scan<<<1, SCAN_T>>>();
    k_scatter<<<edge_blocks, 256>>>();

    for (int l = 0; l < 3; l++) {
        k_gemm<<<gemm_blocks, 256>>>(x, W[l], l == 0 ? 1 : 0);
        k_alpha<<<warp8_blocks, 256>>>(asrc[l], adst[l]);
        k_node<<<warp8_blocks, 256>>>(bias[l]);
    }

    k_zero_pool<<<(GG * HC + 255) / 256, 256>>>();
    k_count<<<node_blocks, 256>>>();
    k_pool<<<nf_blocks, 256>>>();
    k_mlp1<<<GG, L1S>>>(lin1_w, lin1_b);
    k_mlp2<<<GG, 256>>>(lin2_w, lin2_b);
    k_mlp3<<<GG, L2S>>>(out_w, out_b, out);
}

// round 3
// speedup vs baseline: 3.2887x; 1.1231x over previous
#include <cuda_runtime.h>
#include <cuda_bf16.h>
#include <math.h>

// ---------------- problem constants ----------------
#define NN   50000
#define EE   800000
#define EP   (EE + NN)      // 850000
#define HH   2
#define HC   128
#define GG   128
#define L1S  256
#define L2S  128
#define OUTS 10
#define NEG_SLOPE 0.2f

// ---------------- static device scratch ----------------
__device__ int   g_is64;
__device__ int   g_src[EP];
__device__ int   g_dst[EP];
__device__ int   g_bat[NN];
__device__ int   g_deg[NN];
__device__ int   g_fill[NN];
__device__ int   g_ptr[NN + 1];
__device__ int   g_col[EP];
__device__ int   g_gstart[GG + 1];
__device__ float g_in  [NN * HC];
__device__ float g_h   [NN * HC];
__device__ float g_as  [NN * HH];
__device__ float g_ad  [NN * HH];
__device__ float g_e   [EP * HH];     // only used for deg>32 fallback
__device__ float g_pool[GG * HC];     // pooled mean
__device__ float g_g1  [GG * L1S];
__device__ float g_g2  [GG * L2S];

__device__ __forceinline__ float lrelu(float v) {
    return v > 0.f ? v : NEG_SLOPE * v;
}

// ---------------- dtype sniffing + index conversion + degree histogram ----
__global__ void k_detect(const void* edge) {
    if (threadIdx.x == 0 && blockIdx.x == 0) {
        const unsigned long long* q = (const unsigned long long*)edge;
        int is64 = 1;
        for (int i = 0; i < 1024; i++) {
            if (q[i] >> 32) { is64 = 0; break; }
        }
        g_is64 = is64;
    }
}

__global__ void k_zero_deg() {
    int i = blockIdx.x * blockDim.x + threadIdx.x;
    if (i < NN) g_deg[i] = 0;
}

__global__ void k_conv_edges(const void* edge) {
    int i = blockIdx.x * blockDim.x + threadIdx.x;
    if (i >= EP) return;
    int s, d;
    if (i < EE) {
        if (g_is64) {
            const long long* p = (const long long*)edge;
            s = (int)p[i]; d = (int)p[EE + i];
        } else {
            const int* p = (const int*)edge;
            s = p[i]; d = p[EE + i];
        }
    } else {
        s = i - EE; d = i - EE;
    }
    g_src[i] = s; g_dst[i] = d;
    atomicAdd(&g_deg[d], 1);
}

__global__ void k_conv_batch(const void* batch) {
    int i = blockIdx.x * blockDim.x + threadIdx.x;
    if (i >= NN) return;
    int b;
    if (g_is64) b = (int)((const long long*)batch)[i];
    else        b = ((const int*)batch)[i];
    g_bat[i] = b;
}

// graph boundaries from sorted batch
__global__ void k_bounds() {
    int i = blockIdx.x * blockDim.x + threadIdx.x;
    if (i > NN) return;
    if (i == 0) {
        int b0 = g_bat[0];
        for (int g = 0; g <= b0; g++) g_gstart[g] = 0;
    } else if (i == NN) {
        int bl = g_bat[NN - 1];
        for (int g = bl + 1; g <= GG; g++) g_gstart[g] = NN;
    } else {
        int b = g_bat[i], bp = g_bat[i - 1];
        if (b != bp)
            for (int g = bp + 1; g <= b; g++) g_gstart[g] = i;
    }
}

// ---------------- single-block exclusive scan over 50000 degrees ----------
#define SCAN_T 1024
#define SCAN_CH 49
__global__ void k_scan() {
    __shared__ int sh[SCAN_T];
    int t = threadIdx.x;
    int base = t * SCAN_CH;
    int local[SCAN_CH];
    int sum = 0;
#pragma unroll
    for (int i = 0; i < SCAN_CH; i++) {
        int idx = base + i;
        int v = (idx < NN) ? g_deg[idx] : 0;
        local[i] = sum;
        sum += v;
    }
    sh[t] = sum;
    __syncthreads();
    for (int o = 1; o < SCAN_T; o <<= 1) {
        int v = 0;
        if (t >= o) v = sh[t - o];
        __syncthreads();
        if (t >= o) sh[t] += v;
        __syncthreads();
    }
    int off = (t > 0) ? sh[t - 1] : 0;
#pragma unroll
    for (int i = 0; i < SCAN_CH; i++) {
        int idx = base + i;
        if (idx < NN) { g_ptr[idx] = off + local[i]; g_fill[idx] = 0; }
    }
    if (t == SCAN_T - 1) g_ptr[NN] = sh[SCAN_T - 1];
}

__global__ void k_scatter() {
    int i = blockIdx.x * blockDim.x + threadIdx.x;
    if (i >= EP) return;
    int d = g_dst[i];
    int pos = atomicAdd(&g_fill[d], 1);
    g_col[g_ptr[d] + pos] = g_src[i];
}

// ---------------- GEMM: h[M,128] = A[M,128] @ W[128,128] -----------------
// 128x128 tile, BK=16, 256 threads, 8x8 micro-tile
__global__ void __launch_bounds__(256) k_gemm(const float* __restrict__ A,
                                              const float* __restrict__ W,
                                              int use_x) {
    __shared__ float As[16][128 + 4];   // transposed A tile: As[k][row]
    __shared__ float Bs[16][128];
    const float* Ap = use_x ? A : (const float*)g_in;

    int row0 = blockIdx.x * 128;
    int tid = threadIdx.x;

    int tx = tid & 15, ty = tid >> 4;       // 16x16 thread grid
    int cbase = tx * 8, rbase = ty * 8;

    float acc[8][8];
#pragma unroll
    for (int i = 0; i < 8; i++)
#pragma unroll
        for (int j = 0; j < 8; j++) acc[i][j] = 0.f;

    // load indices: 2 float4 per thread per tile for each of A,B
    int ar = tid >> 1;                      // 0..127 (row within tile)
    int ac = (tid & 1) * 8;                 // 0 or 8 (k offset, 2 float4s)
    int br = tid >> 4;                      // 0..15  (k row)
    int bc = (tid & 15) * 8;                // col offset (2 float4s)

    for (int k0 = 0; k0 < 128; k0 += 16) {
        // A tile: rows row0+ar, k = k0+ac .. +7  -> As[k][row]
        int grow = row0 + ar;
        float4 a0, a1;
        if (grow < NN) {
            a0 = *(const float4*)&Ap[grow * HC + k0 + ac];
            a1 = *(const float4*)&Ap[grow * HC + k0 + ac + 4];
        } else {
            a0 = make_float4(0.f, 0.f, 0.f, 0.f);
            a1 = a0;
        }
        As[ac + 0][ar] = a0.x; As[ac + 1][ar] = a0.y;
        As[ac + 2][ar] = a0.z; As[ac + 3][ar] = a0.w;
        As[ac + 4][ar] = a1.x; As[ac + 5][ar] = a1.y;
        As[ac + 6][ar] = a1.z; As[ac + 7][ar] = a1.w;

        // B tile: W[k0+br][bc..bc+7]
        float4 b0 = *(const float4*)&W[(k0 + br) * HC + bc];
        float4 b1 = *(const float4*)&W[(k0 + br) * HC + bc + 4];
        *(float4*)&Bs[br][bc] = b0;
        *(float4*)&Bs[br][bc + 4] = b1;
        __syncthreads();

#pragma unroll
        for (int k = 0; k < 16; k++) {
            float af[8], bf[8];
#pragma unroll
            for (int i = 0; i < 8; i++) af[i] = As[k][rbase + i];
#pragma unroll
            for (int j = 0; j < 8; j++) bf[j] = Bs[k][cbase + j];
#pragma unroll
            for (int i = 0; i < 8; i++)
#pragma unroll
                for (int j = 0; j < 8; j++) acc[i][j] += af[i] * bf[j];
        }
        __syncthreads();
    }

#pragma unroll
    for (int i = 0; i < 8; i++) {
        int grow = row0 + rbase + i;
        if (grow < NN) {
            *(float4*)&g_h[grow * HC + cbase]     = make_float4(acc[i][0], acc[i][1], acc[i][2], acc[i][3]);
            *(float4*)&g_h[grow * HC + cbase + 4] = make_float4(acc[i][4], acc[i][5], acc[i][6], acc[i][7]);
        }
    }
}

// ---------------- alpha_s / alpha_d: warp per node ----------------
__global__ void k_alpha(const float* __restrict__ a_src,
                        const float* __restrict__ a_dst) {
    int warp = (blockIdx.x * blockDim.x + threadIdx.x) >> 5;
    int lane = threadIdx.x & 31;
    if (warp >= NN) return;
    int f = lane * 4;
    int head = f >> 6;
    const float4 hv = *(const float4*)&g_h[warp * HC + f];
    const float4 sv = *(const float4*)&a_src[f];
    const float4 dv = *(const float4*)&a_dst[f];
    float ps = hv.x * sv.x + hv.y * sv.y + hv.z * sv.z + hv.w * sv.w;
    float pd = hv.x * dv.x + hv.y * dv.y + hv.z * dv.z + hv.w * dv.w;
#pragma unroll
    for (int o = 1; o < 16; o <<= 1) {
        ps += __shfl_xor_sync(0xFFFFFFFFu, ps, o);
        pd += __shfl_xor_sync(0xFFFFFFFFu, pd, o);
    }
    if ((lane & 15) == 0) {
        g_as[warp * HH + head] = ps;
        g_ad[warp * HH + head] = pd;
    }
}

// ---------------- fused softmax + aggregation: warp per dst node ---------
__global__ void __launch_bounds__(256) k_node(const float* __restrict__ b) {
    int w = (blockIdx.x * blockDim.x + threadIdx.x) >> 5;
    if (w >= NN) return;
    int lane = threadIdx.x & 31;
    int beg = g_ptr[w], end = g_ptr[w + 1];
    int deg = end - beg;
    float2 ad = *(const float2*)&g_ad[w * 2];

    int f = lane * 4;
    int head = f >> 6;
    float4 acc = make_float4(0.f, 0.f, 0.f, 0.f);

    if (deg <= 32) {
        // ---- register-resident path: one edge per lane ----
        int s = -1;
        float e0 = -INFINITY, e1 = -INFINITY;
        if (lane < deg) {
            s = g_col[beg + lane];
            float2 as = *(const float2*)&g_as[s * 2];
            e0 = lrelu(as.x + ad.x);
            e1 = lrelu(as.y + ad.y);
        }
        float m0 = e0, m1 = e1;
#pragma unroll
        for (int o = 16; o; o >>= 1) {
            m0 = fmaxf(m0, __shfl_xor_sync(0xFFFFFFFFu, m0, o));
            m1 = fmaxf(m1, __shfl_xor_sync(0xFFFFFFFFu, m1, o));
        }
        float x0 = (lane < deg) ? __expf(e0 - m0) : 0.f;
        float x1 = (lane < deg) ? __expf(e1 - m1) : 0.f;
        float s0 = x0, s1 = x1;
#pragma unroll
        for (int o = 16; o; o >>= 1) {
            s0 += __shfl_xor_sync(0xFFFFFFFFu, s0, o);
            s1 += __shfl_xor_sync(0xFFFFFFFFu, s1, o);
        }
        float a0 = x0 / (s0 + 1e-16f);     // this lane's edge weight, head 0
        float a1 = x1 / (s1 + 1e-16f);     // head 1

        for (int j = 0; j < deg; j++) {
            int   sj  = __shfl_sync(0xFFFFFFFFu, s,  j);
            float aj0 = __shfl_sync(0xFFFFFFFFu, a0, j);
            float aj1 = __shfl_sync(0xFFFFFFFFu, a1, j);
            float aj = head ? aj1 : aj0;
            float4 hv = *(const float4*)&g_h[sj * HC + f];
            acc.x += aj * hv.x; acc.y += aj * hv.y;
            acc.z += aj * hv.z; acc.w += aj * hv.w;
        }
    } else {
        // ---- fallback: stage logits in g_e ----
        float m0 = -INFINITY, m1 = -INFINITY;
        for (int j = beg + lane; j < end; j += 32) {
            int s = g_col[j];
            float2 as = *(const float2*)&g_as[s * 2];
            float e0 = lrelu(as.x + ad.x);
            float e1 = lrelu(as.y + ad.y);
            *(float2*)&g_e[j * 2] = make_float2(e0, e1);
            m0 = fmaxf(m0, e0); m1 = fmaxf(m1, e1);
        }
#pragma unroll
        for (int o = 16; o; o >>= 1) {
            m0 = fmaxf(m0, __shfl_xor_sync(0xFFFFFFFFu, m0, o));
            m1 = fmaxf(m1, __shfl_xor_sync(0xFFFFFFFFu, m1, o));
        }
        float s0 = 0.f, s1 = 0.f;
        for (int j = beg + lane; j < end; j += 32) {
            float2 e = *(const float2*)&g_e[j * 2];
            float x0 = __expf(e.x - m0);
            float x1 = __expf(e.y - m1);
            *(float2*)&g_e[j * 2] = make_float2(x0, x1);
            s0 += x0; s1 += x1;
        }
#pragma unroll
        for (int o = 16; o; o >>= 1) {
            s0 += __shfl_xor_sync(0xFFFFFFFFu, s0, o);
            s1 += __shfl_xor_sync(0xFFFFFFFFu, s1, o);
        }
        float inv = (head ? 1.f / (s1 + 1e-16f) : 1.f / (s0 + 1e-16f));
        __syncwarp();
        int j = beg;
        for (; j + 1 < end; j += 2) {
            int s0i = g_col[j];
            int s1i = g_col[j + 1];
            float a0 = g_e[j * 2 + head] * inv;
            float a1 = g_e[(j + 1) * 2 + head] * inv;
            float4 h0 = *(const float4*)&g_h[s0i * HC + f];
            float4 h1 = *(const float4*)&g_h[s1i * HC + f];
            acc.x += a0 * h0.x + a1 * h1.x;
            acc.y += a0 * h0.y + a1 * h1.y;
            acc.z += a0 * h0.z + a1 * h1.z;
            acc.w += a0 * h0.w + a1 * h1.w;
        }
        if (j < end) {
            int s = g_col[j];
            float a = g_e[j * 2 + head] * inv;
            float4 hv = *(const float4*)&g_h[s * HC + f];
            acc.x += a * hv.x; acc.y += a * hv.y;
            acc.z += a * hv.z; acc.w += a * hv.w;
        }
    }

    float4 bb = *(const float4*)&b[f];
    acc.x = fmaxf(acc.x + bb.x, 0.f);
    acc.y = fmaxf(acc.y + bb.y, 0.f);
    acc.z = fmaxf(acc.z + bb.z, 0.f);
    acc.w = fmaxf(acc.w + bb.w, 0.f);
    *(float4*)&g_in[w * HC + f] = acc;
}

// ---------------- segment pool (batch sorted -> contiguous ranges) --------
__global__ void k_pool_seg() {
    int g = blockIdx.x;            // one block per graph, 128 threads
    int f = threadIdx.x;
    int beg = g_gstart[g], end = g_gstart[g + 1];
    float sum = 0.f;
    for (int n = beg; n < end; n++)
        sum += g_in[n * HC + f];
    float cnt = (float)(end - beg);
    g_pool[g * HC + f] = sum / fmaxf(cnt, 1.f);
}

// ---------------- MLP ----------------
__global__ void k_mlp1(const float* __restrict__ w, const float* __restrict__ b) {
    __shared__ float row[HC];
    int g = blockIdx.x, col = threadIdx.x;
    if (col < HC) row[col] = g_pool[g * HC + col];
    __syncthreads();
    float acc = 0.f;
#pragma unroll 4
    for (int k = 0; k < HC; k++) acc += row[k] * w[k * L1S + col];
    acc += b[col];
    g_g1[g * L1S + col] = acc > 0.f ? acc : 0.f;
}
__global__ void k_mlp2(const float* __restrict__ w, const float* __restrict__ b) {
    __shared__ float row[L1S];
    int g = blockIdx.x, tid = threadIdx.x;
    row[tid] = g_g1[g * L1S + tid];
    __syncthreads();
    if (tid < L2S) {
        float acc = 0.f;
#pragma unroll 4
        for (int k = 0; k < L1S; k++) acc += row[k] * w[k * L2S + tid];
        acc += b[tid];
        g_g2[g * L2S + tid] = acc > 0.f ? acc : 0.f;
    }
}
__global__ void k_mlp3(const float* __restrict__ w, const float* __restrict__ b,
                       float* __restrict__ out) {
    __shared__ float row[L2S];
    int g = blockIdx.x, tid = threadIdx.x;
    row[tid] = g_g2[g * L2S + tid];
    __syncthreads();
    if (tid < OUTS) {
        float acc = 0.f;
#pragma unroll 4
        for (int k = 0; k < L2S; k++) acc += row[k] * w[k * OUTS + tid];
        out[g * OUTS + tid] = acc + b[tid];
    }
}

// ---------------- host orchestration ----------------
extern "C" void kernel_launch(void* const* d_in, const int* in_sizes, int n_in,
                              void* d_out, int out_size) {
    const float* x       = (const float*)d_in[0];
    const void*  edge    = d_in[1];
    const void*  batch   = d_in[2];
    const float* W[3]    = {(const float*)d_in[3], (const float*)d_in[7],  (const float*)d_in[11]};
    const float* asrc[3] = {(const float*)d_in[4], (const float*)d_in[8],  (const float*)d_in[12]};
    const float* adst[3] = {(const float*)d_in[5], (const float*)d_in[9],  (const float*)d_in[13]};
    const float* bias[3] = {(const float*)d_in[6], (const float*)d_in[10], (const float*)d_in[14]};
    const float* lin1_w = (const float*)d_in[15];
    const float* lin1_b = (const float*)d_in[16];
    const float* lin2_w = (const float*)d_in[17];
    const float* lin2_b = (const float*)d_in[18];
    const float* out_w  = (const float*)d_in[19];
    const float* out_b  = (const float*)d_in[20];
    float* out = (float*)d_out;

    const int edge_blocks  = (EP + 255) / 256;
    const int node_blocks  = (NN + 255) / 256;
    const int gemm_blocks  = (NN + 127) / 128;
    const int warp8_blocks = (NN + 7) / 8;

    // CSR build (once per launch)
    k_detect<<<1, 32>>>(edge);
    k_zero_deg<<<node_blocks, 256>>>();
    k_conv_edges<<<edge_blocks, 256>>>(edge);
    k_conv_batch<<<node_blocks, 256>>>(batch);
    k_bounds<<<(NN + 256) / 256, 256>>>();
    k_scan<<<1, SCAN_T>>>();
    k_scatter<<<edge_blocks, 256>>>();

    for (int l = 0; l < 3; l++) {
        k_gemm<<<gemm_blocks, 256>>>(x, W[l], l == 0 ? 1 : 0);
        k_alpha<<<warp8_blocks, 256>>>(asrc[l], adst[l]);
        k_node<<<warp8_blocks, 256>>>(bias[l]);
    }

    k_pool_seg<<<GG, HC>>>();
    k_mlp1<<<GG, L1S>>>(lin1_w, lin1_b);
    k_mlp2<<<GG, 256>>>(lin2_w, lin2_b);
    k_mlp3<<<GG, L2S>>>(out_w, out_b, out);
}

// round 4
// speedup vs baseline: 3.4982x; 1.0637x over previous
#include <cuda_runtime.h>
#include <cuda_bf16.h>
#include <math.h>

// ---------------- problem constants ----------------
#define NN   50000
#define EE   800000
#define EP   (EE + NN)      // 850000
#define HH   2
#define HC   128
#define GG   128
#define L1S  256
#define L2S  128
#define OUTS 10
#define NEG_SLOPE 0.2f

// ---------------- static device scratch ----------------
__device__ int   g_is64;
__device__ int   g_src[EP];
__device__ int   g_dst[EP];
__device__ int   g_deg[NN];
__device__ int   g_fill[NN];
__device__ int   g_ptr[NN + 1];
__device__ int   g_col[EP];
__device__ int   g_gstart[GG + 1];
__device__ float g_in  [NN * HC];
__device__ float g_h   [NN * HC];
__device__ float g_as  [NN * HH];
__device__ float g_ad  [NN * HH];
__device__ float g_e   [EP * HH];     // deg>32 fallback only
__device__ float g_g1  [GG * L1S];

__device__ __forceinline__ float lrelu(float v) {
    return v > 0.f ? v : NEG_SLOPE * v;
}

// ---------------- dtype sniffing ----------------
__global__ void k_detect(const void* edge) {
    if (threadIdx.x == 0 && blockIdx.x == 0) {
        const unsigned long long* q = (const unsigned long long*)edge;
        int is64 = 1;
        for (int i = 0; i < 1024; i++) {
            if (q[i] >> 32) { is64 = 0; break; }
        }
        g_is64 = is64;
    }
}

// ---------------- node prep: zero degrees + graph boundaries -------------
__device__ __forceinline__ int load_idx(const void* p, int i, int is64) {
    return is64 ? (int)((const long long*)p)[i] : ((const int*)p)[i];
}

__global__ void k_prep(const void* batch) {
    int i = blockIdx.x * blockDim.x + threadIdx.x;
    if (i < NN) g_deg[i] = 0;
    if (i > NN) return;
    int is64 = g_is64;
    if (i == 0) {
        int b0 = load_idx(batch, 0, is64);
        for (int g = 0; g <= b0; g++) g_gstart[g] = 0;
    } else {
        int bp = load_idx(batch, i - 1, is64);
        if (i == NN) {
            for (int g = bp + 1; g <= GG; g++) g_gstart[g] = NN;
        } else {
            int b = load_idx(batch, i, is64);
            if (b != bp)
                for (int g = bp + 1; g <= b; g++) g_gstart[g] = i;
        }
    }
}

__global__ void k_conv_edges(const void* edge) {
    int i = blockIdx.x * blockDim.x + threadIdx.x;
    if (i >= EP) return;
    int s, d;
    if (i < EE) {
        if (g_is64) {
            const long long* p = (const long long*)edge;
            s = (int)p[i]; d = (int)p[EE + i];
        } else {
            const int* p = (const int*)edge;
            s = p[i]; d = p[EE + i];
        }
    } else {
        s = i - EE; d = i - EE;
    }
    g_src[i] = s; g_dst[i] = d;
    atomicAdd(&g_deg[d], 1);
}

// ---------------- single-block exclusive scan over degrees ----------
#define SCAN_T 1024
#define SCAN_CH 49
__global__ void k_scan() {
    __shared__ int sh[SCAN_T];
    int t = threadIdx.x;
    int base = t * SCAN_CH;
    int local[SCAN_CH];
    int sum = 0;
#pragma unroll
    for (int i = 0; i < SCAN_CH; i++) {
        int idx = base + i;
        int v = (idx < NN) ? g_deg[idx] : 0;
        local[i] = sum;
        sum += v;
    }
    sh[t] = sum;
    __syncthreads();
    for (int o = 1; o < SCAN_T; o <<= 1) {
        int v = 0;
        if (t >= o) v = sh[t - o];
        __syncthreads();
        if (t >= o) sh[t] += v;
        __syncthreads();
    }
    int off = (t > 0) ? sh[t - 1] : 0;
#pragma unroll
    for (int i = 0; i < SCAN_CH; i++) {
        int idx = base + i;
        if (idx < NN) { g_ptr[idx] = off + local[i]; g_fill[idx] = 0; }
    }
    if (t == SCAN_T - 1) g_ptr[NN] = sh[SCAN_T - 1];
}

__global__ void k_scatter() {
    int i = blockIdx.x * blockDim.x + threadIdx.x;
    if (i >= EP) return;
    int d = g_dst[i];
    int pos = atomicAdd(&g_fill[d], 1);
    g_col[g_ptr[d] + pos] = g_src[i];
}

// ---------------- GEMM + fused alpha epilogue -----------------------------
// h[M,128] = A[M,128] @ W[128,128]; alpha_s/d[row][head] = sum_c h*a_{s,d}
__global__ void __launch_bounds__(256) k_gemm(const float* __restrict__ A,
                                              const float* __restrict__ W,
                                              const float* __restrict__ a_src,
                                              const float* __restrict__ a_dst,
                                              int use_x) {
    __shared__ float As[16][128 + 4];
    __shared__ float Bs[16][128];
    const float* Ap = use_x ? A : (const float*)g_in;

    int row0 = blockIdx.x * 128;
    int tid = threadIdx.x;
    int tx = tid & 15, ty = tid >> 4;
    int cbase = tx * 8, rbase = ty * 8;

    float acc[8][8];
#pragma unroll
    for (int i = 0; i < 8; i++)
#pragma unroll
        for (int j = 0; j < 8; j++) acc[i][j] = 0.f;

    int ar = tid >> 1;
    int ac = (tid & 1) * 8;
    int br = tid >> 4;
    int bc = (tid & 15) * 8;

    for (int k0 = 0; k0 < 128; k0 += 16) {
        int grow = row0 + ar;
        float4 a0, a1;
        if (grow < NN) {
            a0 = *(const float4*)&Ap[grow * HC + k0 + ac];
            a1 = *(const float4*)&Ap[grow * HC + k0 + ac + 4];
        } else {
            a0 = make_float4(0.f, 0.f, 0.f, 0.f);
            a1 = a0;
        }
        As[ac + 0][ar] = a0.x; As[ac + 1][ar] = a0.y;
        As[ac + 2][ar] = a0.z; As[ac + 3][ar] = a0.w;
        As[ac + 4][ar] = a1.x; As[ac + 5][ar] = a1.y;
        As[ac + 6][ar] = a1.z; As[ac + 7][ar] = a1.w;

        *(float4*)&Bs[br][bc]     = *(const float4*)&W[(k0 + br) * HC + bc];
        *(float4*)&Bs[br][bc + 4] = *(const float4*)&W[(k0 + br) * HC + bc + 4];
        __syncthreads();

#pragma unroll
        for (int k = 0; k < 16; k++) {
            float af[8], bf[8];
#pragma unroll
            for (int i = 0; i < 8; i++) af[i] = As[k][rbase + i];
#pragma unroll
            for (int j = 0; j < 8; j++) bf[j] = Bs[k][cbase + j];
#pragma unroll
            for (int i = 0; i < 8; i++)
#pragma unroll
                for (int j = 0; j < 8; j++) acc[i][j] += af[i] * bf[j];
        }
        __syncthreads();
    }

    // store h
#pragma unroll
    for (int i = 0; i < 8; i++) {
        int grow = row0 + rbase + i;
        if (grow < NN) {
            *(float4*)&g_h[grow * HC + cbase]     = make_float4(acc[i][0], acc[i][1], acc[i][2], acc[i][3]);
            *(float4*)&g_h[grow * HC + cbase + 4] = make_float4(acc[i][4], acc[i][5], acc[i][6], acc[i][7]);
        }
    }

    // fused alpha: per row, dot over this thread's 8 cols, reduce across
    // the 8-lane tx-group that spans one head's 64 columns.
    float sv[8], dv[8];
#pragma unroll
    for (int j = 0; j < 8; j++) {
        sv[j] = a_src[cbase + j];
        dv[j] = a_dst[cbase + j];
    }
    int lane = tid & 31;
    int head = tx >> 3;
#pragma unroll
    for (int i = 0; i < 8; i++) {
        float ps = 0.f, pd = 0.f;
#pragma unroll
        for (int j = 0; j < 8; j++) {
            ps += acc[i][j] * sv[j];
            pd += acc[i][j] * dv[j];
        }
#pragma unroll
        for (int o = 1; o < 8; o <<= 1) {
            ps += __shfl_xor_sync(0xFFFFFFFFu, ps, o);
            pd += __shfl_xor_sync(0xFFFFFFFFu, pd, o);
        }
        if ((lane & 7) == 0) {
            int grow = row0 + rbase + i;
            if (grow < NN) {
                g_as[grow * HH + head] = ps;
                g_ad[grow * HH + head] = pd;
            }
        }
    }
}

// ---------------- fused softmax + aggregation: warp per dst node ---------
__global__ void __launch_bounds__(256) k_node(const float* __restrict__ b) {
    __shared__ int    sh_s[8][32];
    __shared__ float2 sh_a[8][32];
    int w = (blockIdx.x * blockDim.x + threadIdx.x) >> 5;
    if (w >= NN) return;
    int lane = threadIdx.x & 31;
    int wl = (threadIdx.x >> 5);
    int beg = g_ptr[w], end = g_ptr[w + 1];
    int deg = end - beg;
    float2 ad = *(const float2*)&g_ad[w * 2];

    int f = lane * 4;
    int head = f >> 6;
    float4 acc = make_float4(0.f, 0.f, 0.f, 0.f);

    if (deg <= 32) {
        // ---- register/smem-resident path ----
        int s = 0;
        float e0 = -INFINITY, e1 = -INFINITY;
        if (lane < deg) {
            s = g_col[beg + lane];
            float2 as = *(const float2*)&g_as[s * 2];
            e0 = lrelu(as.x + ad.x);
            e1 = lrelu(as.y + ad.y);
        }
        float m0 = e0, m1 = e1;
#pragma unroll
        for (int o = 16; o; o >>= 1) {
            m0 = fmaxf(m0, __shfl_xor_sync(0xFFFFFFFFu, m0, o));
            m1 = fmaxf(m1, __shfl_xor_sync(0xFFFFFFFFu, m1, o));
        }
        float x0 = (lane < deg) ? __expf(e0 - m0) : 0.f;
        float x1 = (lane < deg) ? __expf(e1 - m1) : 0.f;
        float s0 = x0, s1 = x1;
#pragma unroll
        for (int o = 16; o; o >>= 1) {
            s0 += __shfl_xor_sync(0xFFFFFFFFu, s0, o);
            s1 += __shfl_xor_sync(0xFFFFFFFFu, s1, o);
        }
        sh_s[wl][lane] = s;
        sh_a[wl][lane] = make_float2(x0 / (s0 + 1e-16f), x1 / (s1 + 1e-16f));
        __syncwarp();

        // gather, 4 edges in flight
        int j = 0;
        for (; j + 3 < deg; j += 4) {
            int    i0 = sh_s[wl][j],     i1 = sh_s[wl][j + 1];
            int    i2 = sh_s[wl][j + 2], i3 = sh_s[wl][j + 3];
            float2 w0 = sh_a[wl][j],     w1 = sh_a[wl][j + 1];
            float2 w2 = sh_a[wl][j + 2], w3 = sh_a[wl][j + 3];
            float a0 = head ? w0.y : w0.x;
            float a1 = head ? w1.y : w1.x;
            float a2 = head ? w2.y : w2.x;
            float a3 = head ? w3.y : w3.x;
            float4 h0 = *(const float4*)&g_h[i0 * HC + f];
            float4 h1 = *(const float4*)&g_h[i1 * HC + f];
            float4 h2 = *(const float4*)&g_h[i2 * HC + f];
            float4 h3 = *(const float4*)&g_h[i3 * HC + f];
            acc.x += a0 * h0.x + a1 * h1.x + a2 * h2.x + a3 * h3.x;
            acc.y += a0 * h0.y + a1 * h1.y + a2 * h2.y + a3 * h3.y;
            acc.z += a0 * h0.z + a1 * h1.z + a2 * h2.z + a3 * h3.z;
            acc.w += a0 * h0.w + a1 * h1.w + a2 * h2.w + a3 * h3.w;
        }
        for (; j < deg; j++) {
            int    sj = sh_s[wl][j];
            float2 wj = sh_a[wl][j];
            float  aj = head ? wj.y : wj.x;
            float4 hv = *(const float4*)&g_h[sj * HC + f];
            acc.x += aj * hv.x; acc.y += aj * hv.y;
            acc.z += aj * hv.z; acc.w += aj * hv.w;
        }
    } else {
        // ---- rare fallback: stage logits in g_e ----
        float m0 = -INFINITY, m1 = -INFINITY;
        for (int j = beg + lane; j < end; j += 32) {
            int s = g_col[j];
            float2 as = *(const float2*)&g_as[s * 2];
            float e0 = lrelu(as.x + ad.x);
            float e1 = lrelu(as.y + ad.y);
            *(float2*)&g_e[j * 2] = make_float2(e0, e1);
            m0 = fmaxf(m0, e0); m1 = fmaxf(m1, e1);
        }
#pragma unroll
        for (int o = 16; o; o >>= 1) {
            m0 = fmaxf(m0, __shfl_xor_sync(0xFFFFFFFFu, m0, o));
            m1 = fmaxf(m1, __shfl_xor_sync(0xFFFFFFFFu, m1, o));
        }
        float s0 = 0.f, s1 = 0.f;
        for (int j = beg + lane; j < end; j += 32) {
            float2 e = *(const float2*)&g_e[j * 2];
            float x0 = __expf(e.x - m0);
            float x1 = __expf(e.y - m1);
            *(float2*)&g_e[j * 2] = make_float2(x0, x1);
            s0 += x0; s1 += x1;
        }
#pragma unroll
        for (int o = 16; o; o >>= 1) {
            s0 += __shfl_xor_sync(0xFFFFFFFFu, s0, o);
            s1 += __shfl_xor_sync(0xFFFFFFFFu, s1, o);
        }
        float inv = head ? 1.f / (s1 + 1e-16f) : 1.f / (s0 + 1e-16f);
        __syncwarp();
        int j = beg;
        for (; j + 1 < end; j += 2) {
            int s0i = g_col[j];
            int s1i = g_col[j + 1];
            float a0 = g_e[j * 2 + head] * inv;
            float a1 = g_e[(j + 1) * 2 + head] * inv;
            float4 h0 = *(const float4*)&g_h[s0i * HC + f];
            float4 h1 = *(const float4*)&g_h[s1i * HC + f];
            acc.x += a0 * h0.x + a1 * h1.x;
            acc.y += a0 * h0.y + a1 * h1.y;
            acc.z += a0 * h0.z + a1 * h1.z;
            acc.w += a0 * h0.w + a1 * h1.w;
        }
        if (j < end) {
            int s = g_col[j];
            float a = g_e[j * 2 + head] * inv;
            float4 hv = *(const float4*)&g_h[s * HC + f];
            acc.x += a * hv.x; acc.y += a * hv.y;
            acc.z += a * hv.z; acc.w += a * hv.w;
        }
    }

    float4 bb = *(const float4*)&b[f];
    acc.x = fmaxf(acc.x + bb.x, 0.f);
    acc.y = fmaxf(acc.y + bb.y, 0.f);
    acc.z = fmaxf(acc.z + bb.z, 0.f);
    acc.w = fmaxf(acc.w + bb.w, 0.f);
    *(float4*)&g_in[w * HC + f] = acc;
}

// ---------------- fused pool + MLP head: one block per graph --------------
__global__ void __launch_bounds__(256) k_head(
        const float* __restrict__ w1, const float* __restrict__ b1,
        const float* __restrict__ w2, const float* __restrict__ b2,
        const float* __restrict__ w3, const float* __restrict__ b3,
        float* __restrict__ out) {
    __shared__ float pool[HC];
    __shared__ float r1[L1S];
    __shared__ float r2[L2S];
    int g = blockIdx.x, tid = threadIdx.x;
    int beg = g_gstart[g], end = g_gstart[g + 1];

    if (tid < HC) {
        float sum = 0.f;
        for (int n = beg; n < end; n++) sum += g_in[n * HC + tid];
        pool[tid] = sum / fmaxf((float)(end - beg), 1.f);
    }
    __syncthreads();

    {   // L1: 256 outputs
        float acc = 0.f;
#pragma unroll 4
        for (int k = 0; k < HC; k++) acc += pool[k] * w1[k * L1S + tid];
        acc += b1[tid];
        r1[tid] = acc > 0.f ? acc : 0.f;
    }
    __syncthreads();

    if (tid < L2S) {
        float acc = 0.f;
#pragma unroll 4
        for (int k = 0; k < L1S; k++) acc += r1[k] * w2[k * L2S + tid];
        acc += b2[tid];
        r2[tid] = acc > 0.f ? acc : 0.f;
    }
    __syncthreads();

    if (tid < OUTS) {
        float acc = 0.f;
#pragma unroll 4
        for (int k = 0; k < L2S; k++) acc += r2[k] * w3[k * OUTS + tid];
        out[g * OUTS + tid] = acc + b3[tid];
    }
}

// ---------------- host orchestration ----------------
extern "C" void kernel_launch(void* const* d_in, const int* in_sizes, int n_in,
                              void* d_out, int out_size) {
    const float* x       = (const float*)d_in[0];
    const void*  edge    = d_in[1];
    const void*  batch   = d_in[2];
    const float* W[3]    = {(const float*)d_in[3], (const float*)d_in[7],  (const float*)d_in[11]};
    const float* asrc[3] = {(const float*)d_in[4], (const float*)d_in[8],  (const float*)d_in[12]};
    const float* adst[3] = {(const float*)d_in[5], (const float*)d_in[9],  (const float*)d_in[13]};
    const float* bias[3] = {(const float*)d_in[6], (const float*)d_in[10], (const float*)d_in[14]};
    const float* lin1_w = (const float*)d_in[15];
    const float* lin1_b = (const float*)d_in[16];
    const float* lin2_w = (const float*)d_in[17];
    const float* lin2_b = (const float*)d_in[18];
    const float* out_w  = (const float*)d_in[19];
    const float* out_b  = (const float*)d_in[20];
    float* out = (float*)d_out;

    const int edge_blocks  = (EP + 255) / 256;
    const int gemm_blocks  = (NN + 127) / 128;
    const int warp8_blocks = (NN + 7) / 8;

    k_detect<<<1, 32>>>(edge);
    k_prep<<<(NN + 256) / 256, 256>>>(batch);
    k_conv_edges<<<edge_blocks, 256>>>(edge);
    k_scan<<<1, SCAN_T>>>();
    k_scatter<<<edge_blocks, 256>>>();

    for (int l = 0; l < 3; l++) {
        k_gemm<<<gemm_blocks, 256>>>(x, W[l], asrc[l], adst[l], l == 0 ? 1 : 0);
        k_node<<<warp8_blocks, 256>>>(bias[l]);
    }

    k_head<<<GG, 256>>>(lin1_w, lin1_b, lin2_w, lin2_b, out_w, out_b, out);
}

// round 5
// speedup vs baseline: 3.9848x; 1.1391x over previous
#include <cuda_runtime.h>
#include <cuda_bf16.h>
#include <math.h>

// ---------------- problem constants ----------------
#define NN   50000
#define EE   800000
#define EP   (EE + NN)      // 850000
#define HH   2
#define HC   128
#define GG   128
#define L1S  256
#define L2S  128
#define OUTS 10
#define NEG_SLOPE 0.2f
#define NB   49             // scan blocks: 49*1024 >= NN

// ---------------- static device scratch ----------------
__device__ int   g_is64;
__device__ int   g_deg[NN];
__device__ int   g_fill[NN];
__device__ int   g_ptr[NN + 1];
__device__ int   g_col[EP];
__device__ int   g_bsum[NB];
__device__ int   g_boff[NB];
__device__ int   g_gstart[GG + 1];
__device__ float g_in  [NN * HC];
__device__ float g_h   [NN * HC];
__device__ float g_as  [NN * HH];
__device__ float g_ad  [NN * HH];
__device__ float g_e   [EP * HH];     // deg>32 fallback only

__device__ __forceinline__ float lrelu(float v) {
    return v > 0.f ? v : NEG_SLOPE * v;
}

__device__ __forceinline__ int load_idx(const void* p, long long i, int is64) {
    return is64 ? (int)((const long long*)p)[i] : ((const int*)p)[i];
}

// ---------------- dtype sniffing (parallel) ----------------
__global__ void k_detect(const void* edge) {
    __shared__ int any_hi;
    int tid = threadIdx.x;
    if (tid == 0) any_hi = 0;
    __syncthreads();
    const unsigned long long* q = (const unsigned long long*)edge;
    int bad = 0;
    for (int i = tid; i < 1024; i += 256)
        if (q[i] >> 32) bad = 1;
    if (bad) any_hi = 1;
    __syncthreads();
    if (tid == 0) g_is64 = any_hi ? 0 : 1;
}

// ---------------- node prep: zero degrees + graph boundaries -------------
__global__ void k_prep(const void* batch) {
    int i = blockIdx.x * blockDim.x + threadIdx.x;
    if (i < NN) g_deg[i] = 0;
    if (i > NN) return;
    int is64 = g_is64;
    if (i == 0) {
        int b0 = load_idx(batch, 0, is64);
        for (int g = 0; g <= b0; g++) g_gstart[g] = 0;
    } else {
        int bp = load_idx(batch, i - 1, is64);
        if (i == NN) {
            for (int g = bp + 1; g <= GG; g++) g_gstart[g] = NN;
        } else {
            int b = load_idx(batch, i, is64);
            if (b != bp)
                for (int g = bp + 1; g <= b; g++) g_gstart[g] = i;
        }
    }
}

// ---------------- degree histogram (reads raw edges) ----------------
__global__ void k_deg(const void* edge) {
    int i = blockIdx.x * blockDim.x + threadIdx.x;
    if (i >= EP) return;
    int d;
    if (i < EE) d = load_idx(edge, (long long)EE + i, g_is64);
    else        d = i - EE;
    atomicAdd(&g_deg[d], 1);
}

// ---------------- multi-block exclusive scan ----------------
__global__ void __launch_bounds__(1024) k_scanA() {
    __shared__ int wsum[32];
    int i = blockIdx.x * 1024 + threadIdx.x;
    int lane = threadIdx.x & 31, wid = threadIdx.x >> 5;
    int v = (i < NN) ? g_deg[i] : 0;
    int inc = v;
#pragma unroll
    for (int o = 1; o < 32; o <<= 1) {
        int t = __shfl_up_sync(0xFFFFFFFFu, inc, o);
        if (lane >= o) inc += t;
    }
    if (lane == 31) wsum[wid] = inc;
    __syncthreads();
    if (wid == 0) {
        int wv = wsum[lane];
        int winc = wv;
#pragma unroll
        for (int o = 1; o < 32; o <<= 1) {
            int t = __shfl_up_sync(0xFFFFFFFFu, winc, o);
            if (lane >= o) winc += t;
        }
        wsum[lane] = winc - wv;                 // exclusive warp offset
        if (lane == 31) g_bsum[blockIdx.x] = winc;  // block total
    }
    __syncthreads();
    int ex = inc - v + wsum[wid];
    if (i < NN) g_ptr[i] = ex;
}

__global__ void k_scanB() {
    __shared__ int s[64];
    int t = threadIdx.x;                        // 64 threads
    int v = (t < NB) ? g_bsum[t] : 0;
    s[t] = v;
    __syncthreads();
    for (int o = 1; o < 64; o <<= 1) {
        int x = (t >= o) ? s[t - o] : 0;
        __syncthreads();
        s[t] += x;
        __syncthreads();
    }
    if (t < NB) g_boff[t] = s[t] - v;
    if (t == 63) g_ptr[NN] = s[63];
}

__global__ void __launch_bounds__(1024) k_scanC() {
    int i = blockIdx.x * 1024 + threadIdx.x;
    if (i >= NN) return;
    g_ptr[i] += g_boff[i >> 10];
    g_fill[i] = 0;
}

// ---------------- scatter into CSR (reads raw edges) ----------------
__global__ void k_scatter(const void* edge) {
    int i = blockIdx.x * blockDim.x + threadIdx.x;
    if (i >= EP) return;
    int s, d;
    if (i < EE) {
        int is64 = g_is64;
        s = load_idx(edge, i, is64);
        d = load_idx(edge, (long long)EE + i, is64);
    } else {
        s = i - EE; d = s;
    }
    int pos = atomicAdd(&g_fill[d], 1);
    g_col[g_ptr[d] + pos] = s;
}

// ---------------- GEMM + fused alpha epilogue -----------------------------
__global__ void __launch_bounds__(256) k_gemm(const float* __restrict__ A,
                                              const float* __restrict__ W,
                                              const float* __restrict__ a_src,
                                              const float* __restrict__ a_dst,
                                              int use_x) {
    __shared__ float As[16][128 + 4];
    __shared__ float Bs[16][128];
    const float* Ap = use_x ? A : (const float*)g_in;

    int row0 = blockIdx.x * 128;
    int tid = threadIdx.x;
    int tx = tid & 15, ty = tid >> 4;
    int cbase = tx * 8, rbase = ty * 8;

    float acc[8][8];
#pragma unroll
    for (int i = 0; i < 8; i++)
#pragma unroll
        for (int j = 0; j < 8; j++) acc[i][j] = 0.f;

    int ar = tid >> 1;
    int ac = (tid & 1) * 8;
    int br = tid >> 4;
    int bc = (tid & 15) * 8;

    for (int k0 = 0; k0 < 128; k0 += 16) {
        int grow = row0 + ar;
        float4 a0, a1;
        if (grow < NN) {
            a0 = *(const float4*)&Ap[grow * HC + k0 + ac];
            a1 = *(const float4*)&Ap[grow * HC + k0 + ac + 4];
        } else {
            a0 = make_float4(0.f, 0.f, 0.f, 0.f);
            a1 = a0;
        }
        As[ac + 0][ar] = a0.x; As[ac + 1][ar] = a0.y;
        As[ac + 2][ar] = a0.z; As[ac + 3][ar] = a0.w;
        As[ac + 4][ar] = a1.x; As[ac + 5][ar] = a1.y;
        As[ac + 6][ar] = a1.z; As[ac + 7][ar] = a1.w;

        *(float4*)&Bs[br][bc]     = *(const float4*)&W[(k0 + br) * HC + bc];
        *(float4*)&Bs[br][bc + 4] = *(const float4*)&W[(k0 + br) * HC + bc + 4];
        __syncthreads();

#pragma unroll
        for (int k = 0; k < 16; k++) {
            float af[8], bf[8];
#pragma unroll
            for (int i = 0; i < 8; i++) af[i] = As[k][rbase + i];
#pragma unroll
            for (int j = 0; j < 8; j++) bf[j] = Bs[k][cbase + j];
#pragma unroll
            for (int i = 0; i < 8; i++)
#pragma unroll
                for (int j = 0; j < 8; j++) acc[i][j] += af[i] * bf[j];
        }
        __syncthreads();
    }

#pragma unroll
    for (int i = 0; i < 8; i++) {
        int grow = row0 + rbase + i;
        if (grow < NN) {
            *(float4*)&g_h[grow * HC + cbase]     = make_float4(acc[i][0], acc[i][1], acc[i][2], acc[i][3]);
            *(float4*)&g_h[grow * HC + cbase + 4] = make_float4(acc[i][4], acc[i][5], acc[i][6], acc[i][7]);
        }
    }

    float sv[8], dv[8];
#pragma unroll
    for (int j = 0; j < 8; j++) {
        sv[j] = a_src[cbase + j];
        dv[j] = a_dst[cbase + j];
    }
    int lane = tid & 31;
    int head = tx >> 3;
#pragma unroll
    for (int i = 0; i < 8; i++) {
        float ps = 0.f, pd = 0.f;
#pragma unroll
        for (int j = 0; j < 8; j++) {
            ps += acc[i][j] * sv[j];
            pd += acc[i][j] * dv[j];
        }
#pragma unroll
        for (int o = 1; o < 8; o <<= 1) {
            ps += __shfl_xor_sync(0xFFFFFFFFu, ps, o);
            pd += __shfl_xor_sync(0xFFFFFFFFu, pd, o);
        }
        if ((lane & 7) == 0) {
            int grow = row0 + rbase + i;
            if (grow < NN) {
                g_as[grow * HH + head] = ps;
                g_ad[grow * HH + head] = pd;
            }
        }
    }
}

// ---------------- fused softmax + aggregation: warp per dst node ---------
__global__ void __launch_bounds__(256) k_node(const float* __restrict__ b) {
    __shared__ int    sh_s[8][32];
    __shared__ float2 sh_a[8][32];
    int w = (blockIdx.x * blockDim.x + threadIdx.x) >> 5;
    if (w >= NN) return;
    int lane = threadIdx.x & 31;
    int wl = (threadIdx.x >> 5);
    int beg = g_ptr[w], end = g_ptr[w + 1];
    int deg = end - beg;
    float2 ad = *(const float2*)&g_ad[w * 2];

    int f = lane * 4;
    int head = f >> 6;
    float4 acc = make_float4(0.f, 0.f, 0.f, 0.f);

    if (deg <= 32) {
        int s = 0;
        float e0 = -INFINITY, e1 = -INFINITY;
        if (lane < deg) {
            s = g_col[beg + lane];
            float2 as = *(const float2*)&g_as[s * 2];
            e0 = lrelu(as.x + ad.x);
            e1 = lrelu(as.y + ad.y);
        }
        float m0 = e0, m1 = e1;
#pragma unroll
        for (int o = 16; o; o >>= 1) {
            m0 = fmaxf(m0, __shfl_xor_sync(0xFFFFFFFFu, m0, o));
            m1 = fmaxf(m1, __shfl_xor_sync(0xFFFFFFFFu, m1, o));
        }
        float x0 = (lane < deg) ? __expf(e0 - m0) : 0.f;
        float x1 = (lane < deg) ? __expf(e1 - m1) : 0.f;
        float s0 = x0, s1 = x1;
#pragma unroll
        for (int o = 16; o; o >>= 1) {
            s0 += __shfl_xor_sync(0xFFFFFFFFu, s0, o);
            s1 += __shfl_xor_sync(0xFFFFFFFFu, s1, o);
        }
        sh_s[wl][lane] = s;
        sh_a[wl][lane] = make_float2(x0 / (s0 + 1e-16f), x1 / (s1 + 1e-16f));
        __syncwarp();

        int j = 0;
        for (; j + 3 < deg; j += 4) {
            int    i0 = sh_s[wl][j],     i1 = sh_s[wl][j + 1];
            int    i2 = sh_s[wl][j + 2], i3 = sh_s[wl][j + 3];
            float2 w0 = sh_a[wl][j],     w1 = sh_a[wl][j + 1];
            float2 w2 = sh_a[wl][j + 2], w3 = sh_a[wl][j + 3];
            float a0 = head ? w0.y : w0.x;
            float a1 = head ? w1.y : w1.x;
            float a2 = head ? w2.y : w2.x;
            float a3 = head ? w3.y : w3.x;
            float4 h0 = *(const float4*)&g_h[i0 * HC + f];
            float4 h1 = *(const float4*)&g_h[i1 * HC + f];
            float4 h2 = *(const float4*)&g_h[i2 * HC + f];
            float4 h3 = *(const float4*)&g_h[i3 * HC + f];
            acc.x += a0 * h0.x + a1 * h1.x + a2 * h2.x + a3 * h3.x;
            acc.y += a0 * h0.y + a1 * h1.y + a2 * h2.y + a3 * h3.y;
            acc.z += a0 * h0.z + a1 * h1.z + a2 * h2.z + a3 * h3.z;
            acc.w += a0 * h0.w + a1 * h1.w + a2 * h2.w + a3 * h3.w;
        }
        for (; j < deg; j++) {
            int    sj = sh_s[wl][j];
            float2 wj = sh_a[wl][j];
            float  aj = head ? wj.y : wj.x;
            float4 hv = *(const float4*)&g_h[sj * HC + f];
            acc.x += aj * hv.x; acc.y += aj * hv.y;
            acc.z += aj * hv.z; acc.w += aj * hv.w;
        }
    } else {
        float m0 = -INFINITY, m1 = -INFINITY;
        for (int j = beg + lane; j < end; j += 32) {
            int s = g_col[j];
            float2 as = *(const float2*)&g_as[s * 2];
            float e0 = lrelu(as.x + ad.x);
            float e1 = lrelu(as.y + ad.y);
            *(float2*)&g_e[j * 2] = make_float2(e0, e1);
            m0 = fmaxf(m0, e0); m1 = fmaxf(m1, e1);
        }
#pragma unroll
        for (int o = 16; o; o >>= 1) {
            m0 = fmaxf(m0, __shfl_xor_sync(0xFFFFFFFFu, m0, o));
            m1 = fmaxf(m1, __shfl_xor_sync(0xFFFFFFFFu, m1, o));
        }
        float s0 = 0.f, s1 = 0.f;
        for (int j = beg + lane; j < end; j += 32) {
            float2 e = *(const float2*)&g_e[j * 2];
            float x0 = __expf(e.x - m0);
            float x1 = __expf(e.y - m1);
            *(float2*)&g_e[j * 2] = make_float2(x0, x1);
            s0 += x0; s1 += x1;
        }
#pragma unroll
        for (int o = 16; o; o >>= 1) {
            s0 += __shfl_xor_sync(0xFFFFFFFFu, s0, o);
            s1 += __shfl_xor_sync(0xFFFFFFFFu, s1, o);
        }
        float inv = head ? 1.f / (s1 + 1e-16f) : 1.f / (s0 + 1e-16f);
        __syncwarp();
        int j = beg;
        for (; j + 1 < end; j += 2) {
            int s0i = g_col[j];
            int s1i = g_col[j + 1];
            float a0 = g_e[j * 2 + head] * inv;
            float a1 = g_e[(j + 1) * 2 + head] * inv;
            float4 h0 = *(const float4*)&g_h[s0i * HC + f];
            float4 h1 = *(const float4*)&g_h[s1i * HC + f];
            acc.x += a0 * h0.x + a1 * h1.x;
            acc.y += a0 * h0.y + a1 * h1.y;
            acc.z += a0 * h0.z + a1 * h1.z;
            acc.w += a0 * h0.w + a1 * h1.w;
        }
        if (j < end) {
            int s = g_col[j];
            float a = g_e[j * 2 + head] * inv;
            float4 hv = *(const float4*)&g_h[s * HC + f];
            acc.x += a * hv.x; acc.y += a * hv.y;
            acc.z += a * hv.z; acc.w += a * hv.w;
        }
    }

    float4 bb = *(const float4*)&b[f];
    acc.x = fmaxf(acc.x + bb.x, 0.f);
    acc.y = fmaxf(acc.y + bb.y, 0.f);
    acc.z = fmaxf(acc.z + bb.z, 0.f);
    acc.w = fmaxf(acc.w + bb.w, 0.f);
    *(float4*)&g_in[w * HC + f] = acc;
}

// ---------------- fused pool + MLP head: one block per graph --------------
__global__ void __launch_bounds__(256) k_head(
        const float* __restrict__ w1, const float* __restrict__ b1,
        const float* __restrict__ w2, const float* __restrict__ b2,
        const float* __restrict__ w3, const float* __restrict__ b3,
        float* __restrict__ out) {
    __shared__ float pool[HC];
    __shared__ float r1[L1S];
    __shared__ float r2[L2S];
    int g = blockIdx.x, tid = threadIdx.x;
    int beg = g_gstart[g], end = g_gstart[g + 1];

    if (tid < HC) {
        float sum = 0.f;
        for (int n = beg; n < end; n++) sum += g_in[n * HC + tid];
        pool[tid] = sum / fmaxf((float)(end - beg), 1.f);
    }
    __syncthreads();

    {
        float acc = 0.f;
#pragma unroll 4
        for (int k = 0; k < HC; k++) acc += pool[k] * w1[k * L1S + tid];
        acc += b1[tid];
        r1[tid] = acc > 0.f ? acc : 0.f;
    }
    __syncthreads();

    if (tid < L2S) {
        float acc = 0.f;
#pragma unroll 4
        for (int k = 0; k < L1S; k++) acc += r1[k] * w2[k * L2S + tid];
        acc += b2[tid];
        r2[tid] = acc > 0.f ? acc : 0.f;
    }
    __syncthreads();

    if (tid < OUTS) {
        float acc = 0.f;
#pragma unroll 4
        for (int k = 0; k < L2S; k++) acc += r2[k] * w3[k * OUTS + tid];
        out[g * OUTS + tid] = acc + b3[tid];
    }
}

// ---------------- host orchestration ----------------
extern "C" void kernel_launch(void* const* d_in, const int* in_sizes, int n_in,
                              void* d_out, int out_size) {
    const float* x       = (const float*)d_in[0];
    const void*  edge    = d_in[1];
    const void*  batch   = d_in[2];
    const float* W[3]    = {(const float*)d_in[3], (const float*)d_in[7],  (const float*)d_in[11]};
    const float* asrc[3] = {(const float*)d_in[4], (const float*)d_in[8],  (const float*)d_in[12]};
    const float* adst[3] = {(const float*)d_in[5], (const float*)d_in[9],  (const float*)d_in[13]};
    const float* bias[3] = {(const float*)d_in[6], (const float*)d_in[10], (const float*)d_in[14]};
    const float* lin1_w = (const float*)d_in[15];
    const float* lin1_b = (const float*)d_in[16];
    const float* lin2_w = (const float*)d_in[17];
    const float* lin2_b = (const float*)d_in[18];
    const float* out_w  = (const float*)d_in[19];
    const float* out_b  = (const float*)d_in[20];
    float* out = (float*)d_out;

    const int edge_blocks  = (EP + 255) / 256;
    const int gemm_blocks  = (NN + 127) / 128;
    const int warp8_blocks = (NN + 7) / 8;

    k_detect<<<1, 256>>>(edge);
    k_prep<<<(NN + 256) / 256, 256>>>(batch);
    k_deg<<<edge_blocks, 256>>>(edge);
    k_scanA<<<NB, 1024>>>();
    k_scanB<<<1, 64>>>();
    k_scanC<<<NB, 1024>>>();
    k_scatter<<<edge_blocks, 256>>>(edge);

    for (int l = 0; l < 3; l++) {
        k_gemm<<<gemm_blocks, 256>>>(x, W[l], asrc[l], adst[l], l == 0 ? 1 : 0);
        k_node<<<warp8_blocks, 256>>>(bias[l]);
    }

    k_head<<<GG, 256>>>(lin1_w, lin1_b, lin2_w, lin2_b, out_w, out_b, out);
}

// round 6
// speedup vs baseline: 5.1243x; 1.2860x over previous
#include <cuda_runtime.h>
#include <cuda_bf16.h>
#include <math.h>

// ---------------- problem constants ----------------
#define NN   50000
#define EE   800000
#define EP   (EE + NN)      // 850000
#define HH   2
#define HC   128
#define GG   128
#define L1S  256
#define L2S  128
#define OUTS 10
#define NEG_SLOPE 0.2f
#define NB   49             // scan blocks: 49*1024 >= NN

// ---------------- static device scratch ----------------
__device__ int   g_is64;
__device__ int   g_deg[NN];
__device__ int   g_fill[NN];
__device__ int   g_ptr[NN + 1];
__device__ int   g_col[EP];
__device__ int   g_bsum[NB];
__device__ int   g_boff[NB];
__device__ int   g_gstart[GG + 1];
__device__ float g_in  [NN * HC];
__device__ float g_h   [NN * HC];
__device__ float g_as  [NN * HH];
__device__ float g_ad  [NN * HH];
__device__ float g_e   [EP * HH];     // deg>32 fallback only

__device__ __forceinline__ float lrelu(float v) {
    return v > 0.f ? v : NEG_SLOPE * v;
}

__device__ __forceinline__ int load_idx(const void* p, long long i, int is64) {
    return is64 ? (int)((const long long*)p)[i] : ((const int*)p)[i];
}

__device__ __forceinline__ unsigned f2tf32(float x) {
    unsigned r;
    asm("cvt.rna.tf32.f32 %0, %1;" : "=r"(r) : "f"(x));
    return r;
}

__device__ __forceinline__ void mma_tf32(float* d,
                                         const unsigned* a,
                                         const unsigned* b) {
    asm volatile(
        "mma.sync.aligned.m16n8k8.row.col.f32.tf32.tf32.f32 "
        "{%0,%1,%2,%3}, {%4,%5,%6,%7}, {%8,%9}, {%0,%1,%2,%3};\n"
        : "+f"(d[0]), "+f"(d[1]), "+f"(d[2]), "+f"(d[3])
        : "r"(a[0]), "r"(a[1]), "r"(a[2]), "r"(a[3]),
          "r"(b[0]), "r"(b[1]));
}

// ---------------- dtype sniffing (parallel) ----------------
__global__ void k_detect(const void* edge) {
    __shared__ int any_hi;
    int tid = threadIdx.x;
    if (tid == 0) any_hi = 0;
    __syncthreads();
    const unsigned long long* q = (const unsigned long long*)edge;
    int bad = 0;
    for (int i = tid; i < 1024; i += 256)
        if (q[i] >> 32) bad = 1;
    if (bad) any_hi = 1;
    __syncthreads();
    if (tid == 0) g_is64 = any_hi ? 0 : 1;
}

// ---------------- node prep: zero degrees + graph boundaries -------------
__global__ void k_prep(const void* batch) {
    int i = blockIdx.x * blockDim.x + threadIdx.x;
    if (i < NN) g_deg[i] = 0;
    if (i > NN) return;
    int is64 = g_is64;
    if (i == 0) {
        int b0 = load_idx(batch, 0, is64);
        for (int g = 0; g <= b0; g++) g_gstart[g] = 0;
    } else {
        int bp = load_idx(batch, i - 1, is64);
        if (i == NN) {
            for (int g = bp + 1; g <= GG; g++) g_gstart[g] = NN;
        } else {
            int b = load_idx(batch, i, is64);
            if (b != bp)
                for (int g = bp + 1; g <= b; g++) g_gstart[g] = i;
        }
    }
}

// ---------------- degree histogram ----------------
__global__ void k_deg(const void* edge) {
    int i = blockIdx.x * blockDim.x + threadIdx.x;
    if (i >= EP) return;
    int d;
    if (i < EE) d = load_idx(edge, (long long)EE + i, g_is64);
    else        d = i - EE;
    atomicAdd(&g_deg[d], 1);
}

// ---------------- multi-block exclusive scan ----------------
__global__ void __launch_bounds__(1024) k_scanA() {
    __shared__ int wsum[32];
    int i = blockIdx.x * 1024 + threadIdx.x;
    int lane = threadIdx.x & 31, wid = threadIdx.x >> 5;
    int v = (i < NN) ? g_deg[i] : 0;
    int inc = v;
#pragma unroll
    for (int o = 1; o < 32; o <<= 1) {
        int t = __shfl_up_sync(0xFFFFFFFFu, inc, o);
        if (lane >= o) inc += t;
    }
    if (lane == 31) wsum[wid] = inc;
    __syncthreads();
    if (wid == 0) {
        int wv = wsum[lane];
        int winc = wv;
#pragma unroll
        for (int o = 1; o < 32; o <<= 1) {
            int t = __shfl_up_sync(0xFFFFFFFFu, winc, o);
            if (lane >= o) winc += t;
        }
        wsum[lane] = winc - wv;
        if (lane == 31) g_bsum[blockIdx.x] = winc;
    }
    __syncthreads();
    int ex = inc - v + wsum[wid];
    if (i < NN) g_ptr[i] = ex;
}

__global__ void k_scanB() {
    __shared__ int s[64];
    int t = threadIdx.x;
    int v = (t < NB) ? g_bsum[t] : 0;
    s[t] = v;
    __syncthreads();
    for (int o = 1; o < 64; o <<= 1) {
        int x = (t >= o) ? s[t - o] : 0;
        __syncthreads();
        s[t] += x;
        __syncthreads();
    }
    if (t < NB) g_boff[t] = s[t] - v;
    if (t == 63) g_ptr[NN] = s[63];
}

__global__ void __launch_bounds__(1024) k_scanC() {
    int i = blockIdx.x * 1024 + threadIdx.x;
    if (i >= NN) return;
    g_ptr[i] += g_boff[i >> 10];
    g_fill[i] = 0;
}

// ---------------- scatter into CSR ----------------
__global__ void k_scatter(const void* edge) {
    int i = blockIdx.x * blockDim.x + threadIdx.x;
    if (i >= EP) return;
    int s, d;
    if (i < EE) {
        int is64 = g_is64;
        s = load_idx(edge, i, is64);
        d = load_idx(edge, (long long)EE + i, is64);
    } else {
        s = i - EE; d = s;
    }
    int pos = atomicAdd(&g_fill[d], 1);
    g_col[g_ptr[d] + pos] = s;
}

// ---------------- tf32 tensor-core GEMM + fused alpha ---------------------
// h[M,128] = A[M,128] @ W[128,128]; 128x128 block tile, 8 warps (64x32 each)
#define AS_STRIDE 36      // banks: 4*row + k -> conflict-free
#define BS_STRIDE 136     // banks: 8*k + n  -> conflict-free
__global__ void __launch_bounds__(256) k_gemm(const float* __restrict__ A,
                                              const float* __restrict__ W,
                                              const float* __restrict__ a_src,
                                              const float* __restrict__ a_dst,
                                              int use_x) {
    __shared__ unsigned As[128 * AS_STRIDE];     // [row][k] k-chunk of 32
    __shared__ unsigned Bs[32 * BS_STRIDE];      // [k][n]
    __shared__ float s_as[128][2];
    __shared__ float s_ad[128][2];

    const float* Ap = use_x ? A : (const float*)g_in;
    int row0 = blockIdx.x * 128;
    int tid = threadIdx.x;
    int wid = tid >> 5, lane = tid & 31;
    int g = lane >> 2, t = lane & 3;             // group / tid-in-group
    int wr = wid >> 2, wc = wid & 3;             // warp row(0-1) / col(0-3)
    int head = wc >> 1;

    // zero alpha accumulators
    if (tid < 128) { s_as[tid][0] = 0.f; s_as[tid][1] = 0.f;
                     s_ad[tid][0] = 0.f; s_ad[tid][1] = 0.f; }

    float acc[4][4][4];
#pragma unroll
    for (int mf = 0; mf < 4; mf++)
#pragma unroll
        for (int nf = 0; nf < 4; nf++)
#pragma unroll
            for (int c = 0; c < 4; c++) acc[mf][nf][c] = 0.f;

    for (int k0 = 0; k0 < 128; k0 += 32) {
        // fill As: 128 rows x 32 k = 1024 float4 loads, 4 per thread
#pragma unroll
        for (int l = 0; l < 4; l++) {
            int idx = tid + l * 256;             // 0..1023
            int row = idx >> 3;
            int k4 = (idx & 7) << 2;
            int grow = row0 + row;
            float4 v = (grow < NN) ? *(const float4*)&Ap[grow * HC + k0 + k4]
                                   : make_float4(0.f, 0.f, 0.f, 0.f);
            unsigned* p = &As[row * AS_STRIDE + k4];
            p[0] = f2tf32(v.x); p[1] = f2tf32(v.y);
            p[2] = f2tf32(v.z); p[3] = f2tf32(v.w);
        }
        // fill Bs: 32 k x 128 n = 1024 float4, 4 per thread
#pragma unroll
        for (int l = 0; l < 4; l++) {
            int idx = tid + l * 256;
            int k = idx >> 5;
            int n4 = (idx & 31) << 2;
            float4 v = *(const float4*)&W[(k0 + k) * HC + n4];
            unsigned* p = &Bs[k * BS_STRIDE + n4];
            p[0] = f2tf32(v.x); p[1] = f2tf32(v.y);
            p[2] = f2tf32(v.z); p[3] = f2tf32(v.w);
        }
        __syncthreads();

#pragma unroll
        for (int kk = 0; kk < 32; kk += 8) {
            unsigned af[4][4];
#pragma unroll
            for (int mf = 0; mf < 4; mf++) {
                int r = wr * 64 + mf * 16 + g;
                af[mf][0] = As[r * AS_STRIDE + kk + t];
                af[mf][1] = As[(r + 8) * AS_STRIDE + kk + t];
                af[mf][2] = As[r * AS_STRIDE + kk + t + 4];
                af[mf][3] = As[(r + 8) * AS_STRIDE + kk + t + 4];
            }
            unsigned bf[4][2];
#pragma unroll
            for (int nf = 0; nf < 4; nf++) {
                int n = wc * 32 + nf * 8 + g;
                bf[nf][0] = Bs[(kk + t) * BS_STRIDE + n];
                bf[nf][1] = Bs[(kk + t + 4) * BS_STRIDE + n];
            }
#pragma unroll
            for (int mf = 0; mf < 4; mf++)
#pragma unroll
                for (int nf = 0; nf < 4; nf++)
                    mma_tf32(acc[mf][nf], af[mf], bf[nf]);
        }
        __syncthreads();
    }

    // preload attention vectors for this thread's 8 columns
    float asv[8], adv[8];
#pragma unroll
    for (int nf = 0; nf < 4; nf++) {
#pragma unroll
        for (int c = 0; c < 2; c++) {
            int col = wc * 32 + nf * 8 + 2 * t + c;
            asv[nf * 2 + c] = a_src[col];
            adv[nf * 2 + c] = a_dst[col];
        }
    }

    // store h + alpha partials
#pragma unroll
    for (int mf = 0; mf < 4; mf++) {
#pragma unroll
        for (int r = 0; r < 2; r++) {
            int rloc = wr * 64 + mf * 16 + g + 8 * r;
            int grow = row0 + rloc;
            float ps = 0.f, pd = 0.f;
#pragma unroll
            for (int nf = 0; nf < 4; nf++) {
                float v0 = acc[mf][nf][2 * r];
                float v1 = acc[mf][nf][2 * r + 1];
                ps += v0 * asv[nf * 2] + v1 * asv[nf * 2 + 1];
                pd += v0 * adv[nf * 2] + v1 * adv[nf * 2 + 1];
                if (grow < NN) {
                    int col = wc * 32 + nf * 8 + 2 * t;
                    *(float2*)&g_h[grow * HC + col] = make_float2(v0, v1);
                }
            }
            ps += __shfl_xor_sync(0xFFFFFFFFu, ps, 1);
            ps += __shfl_xor_sync(0xFFFFFFFFu, ps, 2);
            pd += __shfl_xor_sync(0xFFFFFFFFu, pd, 1);
            pd += __shfl_xor_sync(0xFFFFFFFFu, pd, 2);
            if (t == 0) {
                atomicAdd(&s_as[rloc][head], ps);
                atomicAdd(&s_ad[rloc][head], pd);
            }
        }
    }
    __syncthreads();

    if (tid < 128) {
        int grow = row0 + tid;
        if (grow < NN) {
            *(float2*)&g_as[grow * 2] = make_float2(s_as[tid][0], s_as[tid][1]);
            *(float2*)&g_ad[grow * 2] = make_float2(s_ad[tid][0], s_ad[tid][1]);
        }
    }
}

// ---------------- fused softmax + aggregation: warp per dst node ---------
__global__ void __launch_bounds__(256) k_node(const float* __restrict__ b) {
    __shared__ int    sh_s[8][32];
    __shared__ float2 sh_a[8][32];
    int w = (blockIdx.x * blockDim.x + threadIdx.x) >> 5;
    if (w >= NN) return;
    int lane = threadIdx.x & 31;
    int wl = (threadIdx.x >> 5);
    int beg = g_ptr[w], end = g_ptr[w + 1];
    int deg = end - beg;
    float2 ad = *(const float2*)&g_ad[w * 2];

    int f = lane * 4;
    int head = f >> 6;
    float4 acc = make_float4(0.f, 0.f, 0.f, 0.f);

    if (deg <= 32) {
        int s = 0;
        float e0 = -INFINITY, e1 = -INFINITY;
        if (lane < deg) {
            s = g_col[beg + lane];
            float2 as = *(const float2*)&g_as[s * 2];
            e0 = lrelu(as.x + ad.x);
            e1 = lrelu(as.y + ad.y);
        }
        float m0 = e0, m1 = e1;
#pragma unroll
        for (int o = 16; o; o >>= 1) {
            m0 = fmaxf(m0, __shfl_xor_sync(0xFFFFFFFFu, m0, o));
            m1 = fmaxf(m1, __shfl_xor_sync(0xFFFFFFFFu, m1, o));
        }
        float x0 = (lane < deg) ? __expf(e0 - m0) : 0.f;
        float x1 = (lane < deg) ? __expf(e1 - m1) : 0.f;
        float s0 = x0, s1 = x1;
#pragma unroll
        for (int o = 16; o; o >>= 1) {
            s0 += __shfl_xor_sync(0xFFFFFFFFu, s0, o);
            s1 += __shfl_xor_sync(0xFFFFFFFFu, s1, o);
        }
        sh_s[wl][lane] = s;
        sh_a[wl][lane] = make_float2(x0 / (s0 + 1e-16f), x1 / (s1 + 1e-16f));
        __syncwarp();

        int j = 0;
        for (; j + 3 < deg; j += 4) {
            int    i0 = sh_s[wl][j],     i1 = sh_s[wl][j + 1];
            int    i2 = sh_s[wl][j + 2], i3 = sh_s[wl][j + 3];
            float2 w0 = sh_a[wl][j],     w1 = sh_a[wl][j + 1];
            float2 w2 = sh_a[wl][j + 2], w3 = sh_a[wl][j + 3];
            float a0 = head ? w0.y : w0.x;
            float a1 = head ? w1.y : w1.x;
            float a2 = head ? w2.y : w2.x;
            float a3 = head ? w3.y : w3.x;
            float4 h0 = *(const float4*)&g_h[i0 * HC + f];
            float4 h1 = *(const float4*)&g_h[i1 * HC + f];
            float4 h2 = *(const float4*)&g_h[i2 * HC + f];
            float4 h3 = *(const float4*)&g_h[i3 * HC + f];
            acc.x += a0 * h0.x + a1 * h1.x + a2 * h2.x + a3 * h3.x;
            acc.y += a0 * h0.y + a1 * h1.y + a2 * h2.y + a3 * h3.y;
            acc.z += a0 * h0.z + a1 * h1.z + a2 * h2.z + a3 * h3.z;
            acc.w += a0 * h0.w + a1 * h1.w + a2 * h2.w + a3 * h3.w;
        }
        for (; j < deg; j++) {
            int    sj = sh_s[wl][j];
            float2 wj = sh_a[wl][j];
            float  aj = head ? wj.y : wj.x;
            float4 hv = *(const float4*)&g_h[sj * HC + f];
            acc.x += aj * hv.x; acc.y += aj * hv.y;
            acc.z += aj * hv.z; acc.w += aj * hv.w;
        }
    } else {
        float m0 = -INFINITY, m1 = -INFINITY;
        for (int j = beg + lane; j < end; j += 32) {
            int s = g_col[j];
            float2 as = *(const float2*)&g_as[s * 2];
            float e0 = lrelu(as.x + ad.x);
            float e1 = lrelu(as.y + ad.y);
            *(float2*)&g_e[j * 2] = make_float2(e0, e1);
            m0 = fmaxf(m0, e0); m1 = fmaxf(m1, e1);
        }
#pragma unroll
        for (int o = 16; o; o >>= 1) {
            m0 = fmaxf(m0, __shfl_xor_sync(0xFFFFFFFFu, m0, o));
            m1 = fmaxf(m1, __shfl_xor_sync(0xFFFFFFFFu, m1, o));
        }
        float s0 = 0.f, s1 = 0.f;
        for (int j = beg + lane; j < end; j += 32) {
            float2 e = *(const float2*)&g_e[j * 2];
            float x0 = __expf(e.x - m0);
            float x1 = __expf(e.y - m1);
            *(float2*)&g_e[j * 2] = make_float2(x0, x1);
            s0 += x0; s1 += x1;
        }
#pragma unroll
        for (int o = 16; o; o >>= 1) {
            s0 += __shfl_xor_sync(0xFFFFFFFFu, s0, o);
            s1 += __shfl_xor_sync(0xFFFFFFFFu, s1, o);
        }
        float inv = head ? 1.f / (s1 + 1e-16f) : 1.f / (s0 + 1e-16f);
        __syncwarp();
        int j = beg;
        for (; j + 1 < end; j += 2) {
            int s0i = g_col[j];
            int s1i = g_col[j + 1];
            float a0 = g_e[j * 2 + head] * inv;
            float a1 = g_e[(j + 1) * 2 + head] * inv;
            float4 h0 = *(const float4*)&g_h[s0i * HC + f];
            float4 h1 = *(const float4*)&g_h[s1i * HC + f];
            acc.x += a0 * h0.x + a1 * h1.x;
            acc.y += a0 * h0.y + a1 * h1.y;
            acc.z += a0 * h0.z + a1 * h1.z;
            acc.w += a0 * h0.w + a1 * h1.w;
        }
        if (j < end) {
            int s = g_col[j];
            float a = g_e[j * 2 + head] * inv;
            float4 hv = *(const float4*)&g_h[s * HC + f];
            acc.x += a * hv.x; acc.y += a * hv.y;
            acc.z += a * hv.z; acc.w += a * hv.w;
        }
    }

    float4 bb = *(const float4*)&b[f];
    acc.x = fmaxf(acc.x + bb.x, 0.f);
    acc.y = fmaxf(acc.y + bb.y, 0.f);
    acc.z = fmaxf(acc.z + bb.z, 0.f);
    acc.w = fmaxf(acc.w + bb.w, 0.f);
    *(float4*)&g_in[w * HC + f] = acc;
}

// ---------------- fused pool + MLP head ----------------
__global__ void __launch_bounds__(256) k_head(
        const float* __restrict__ w1, const float* __restrict__ b1,
        const float* __restrict__ w2, const float* __restrict__ b2,
        const float* __restrict__ w3, const float* __restrict__ b3,
        float* __restrict__ out) {
    __shared__ float pool[HC];
    __shared__ float r1[L1S];
    __shared__ float r2[L2S];
    int g = blockIdx.x, tid = threadIdx.x;
    int beg = g_gstart[g], end = g_gstart[g + 1];

    if (tid < HC) {
        float sum = 0.f;
        for (int n = beg; n < end; n++) sum += g_in[n * HC + tid];
        pool[tid] = sum / fmaxf((float)(end - beg), 1.f);
    }
    __syncthreads();

    {
        float acc = 0.f;
#pragma unroll 4
        for (int k = 0; k < HC; k++) acc += pool[k] * w1[k * L1S + tid];
        acc += b1[tid];
        r1[tid] = acc > 0.f ? acc : 0.f;
    }
    __syncthreads();

    if (tid < L2S) {
        float acc = 0.f;
#pragma unroll 4
        for (int k = 0; k < L1S; k++) acc += r1[k] * w2[k * L2S + tid];
        acc += b2[tid];
        r2[tid] = acc > 0.f ? acc : 0.f;
    }
    __syncthreads();

    if (tid < OUTS) {
        float acc = 0.f;
#pragma unroll 4
        for (int k = 0; k < L2S; k++) acc += r2[k] * w3[k * OUTS + tid];
        out[g * OUTS + tid] = acc + b3[tid];
    }
}

// ---------------- host orchestration ----------------
extern "C" void kernel_launch(void* const* d_in, const int* in_sizes, int n_in,
                              void* d_out, int out_size) {
    const float* x       = (const float*)d_in[0];
    const void*  edge    = d_in[1];
    const void*  batch   = d_in[2];
    const float* W[3]    = {(const float*)d_in[3], (const float*)d_in[7],  (const float*)d_in[11]};
    const float* asrc[3] = {(const float*)d_in[4], (const float*)d_in[8],  (const float*)d_in[12]};
    const float* adst[3] = {(const float*)d_in[5], (const float*)d_in[9],  (const float*)d_in[13]};
    const float* bias[3] = {(const float*)d_in[6], (const float*)d_in[10], (const float*)d_in[14]};
    const float* lin1_w = (const float*)d_in[15];
    const float* lin1_b = (const float*)d_in[16];
    const float* lin2_w = (const float*)d_in[17];
    const float* lin2_b = (const float*)d_in[18];
    const float* out_w  = (const float*)d_in[19];
    const float* out_b  = (const float*)d_in[20];
    float* out = (float*)d_out;

    const int edge_blocks  = (EP + 255) / 256;
    const int gemm_blocks  = (NN + 127) / 128;
    const int warp8_blocks = (NN + 7) / 8;

    k_detect<<<1, 256>>>(edge);
    k_prep<<<(NN + 256) / 256, 256>>>(batch);
    k_deg<<<edge_blocks, 256>>>(edge);
    k_scanA<<<NB, 1024>>>();
    k_scanB<<<1, 64>>>();
    k_scanC<<<NB, 1024>>>();
    k_scatter<<<edge_blocks, 256>>>(edge);

    for (int l = 0; l < 3; l++) {
        k_gemm<<<gemm_blocks, 256>>>(x, W[l], asrc[l], adst[l], l == 0 ? 1 : 0);
        k_node<<<warp8_blocks, 256>>>(bias[l]);
    }

    k_head<<<GG, 256>>>(lin1_w, lin1_b, lin2_w, lin2_b, out_w, out_b, out);
}

// round 7
// speedup vs baseline: 5.7690x; 1.1258x over previous
#include <cuda_runtime.h>
#include <cuda_bf16.h>
#include <math.h>

// ---------------- problem constants ----------------
#define NN   50000
#define EE   800000
#define EP   (EE + NN)      // 850000
#define HH   2
#define HC   128
#define GG   128
#define L1S  256
#define L2S  128
#define OUTS 10
#define NEG_SLOPE 0.2f
#define NB   49             // scan blocks: 49*1024 >= NN

// ---------------- static device scratch ----------------
__device__ int   g_is64;
__device__ int   g_deg[NN];
__device__ int   g_fill[NN];
__device__ int   g_ptr[NN + 1];
__device__ int   g_col[EP];
__device__ int   g_bsum[NB];
__device__ int   g_boff[NB];
__device__ int   g_gstart[GG + 1];
__device__ float g_in  [NN * HC];
__device__ __nv_bfloat16 g_hb[NN * HC];   // h in bf16 (gather payload)
__device__ float g_as  [NN * HH];
__device__ float g_ad  [NN * HH];
__device__ float g_e   [EP * HH];         // deg>32 fallback only

__device__ __forceinline__ float lrelu(float v) {
    return v > 0.f ? v : NEG_SLOPE * v;
}

__device__ __forceinline__ int load_idx(const void* p, long long i, int is64) {
    return is64 ? (int)((const long long*)p)[i] : ((const int*)p)[i];
}

__device__ __forceinline__ unsigned f2tf32(float x) {
    unsigned r;
    asm("cvt.rna.tf32.f32 %0, %1;" : "=r"(r) : "f"(x));
    return r;
}

__device__ __forceinline__ void mma_tf32(float* d,
                                         const unsigned* a,
                                         const unsigned* b) {
    asm volatile(
        "mma.sync.aligned.m16n8k8.row.col.f32.tf32.tf32.f32 "
        "{%0,%1,%2,%3}, {%4,%5,%6,%7}, {%8,%9}, {%0,%1,%2,%3};\n"
        : "+f"(d[0]), "+f"(d[1]), "+f"(d[2]), "+f"(d[3])
        : "r"(a[0]), "r"(a[1]), "r"(a[2]), "r"(a[3]),
          "r"(b[0]), "r"(b[1]));
}

// gather helper: 4 bf16 features at &g_hb[base], accumulate a*val
__device__ __forceinline__ void acc_bf16(float4& acc, float a, const __nv_bfloat16* p) {
    uint2 raw = *(const uint2*)p;
    __nv_bfloat162 p0 = *reinterpret_cast<__nv_bfloat162*>(&raw.x);
    __nv_bfloat162 p1 = *reinterpret_cast<__nv_bfloat162*>(&raw.y);
    float2 f0 = __bfloat1622float2(p0);
    float2 f1 = __bfloat1622float2(p1);
    acc.x += a * f0.x; acc.y += a * f0.y;
    acc.z += a * f1.x; acc.w += a * f1.y;
}

// ---------------- dtype sniffing (parallel) ----------------
__global__ void k_detect(const void* edge) {
    __shared__ int any_hi;
    int tid = threadIdx.x;
    if (tid == 0) any_hi = 0;
    __syncthreads();
    const unsigned long long* q = (const unsigned long long*)edge;
    int bad = 0;
    for (int i = tid; i < 1024; i += 256)
        if (q[i] >> 32) bad = 1;
    if (bad) any_hi = 1;
    __syncthreads();
    if (tid == 0) g_is64 = any_hi ? 0 : 1;
}

// ---------------- node prep: zero degrees + graph boundaries -------------
__global__ void k_prep(const void* batch) {
    int i = blockIdx.x * blockDim.x + threadIdx.x;
    if (i < NN) g_deg[i] = 0;
    if (i > NN) return;
    int is64 = g_is64;
    if (i == 0) {
        int b0 = load_idx(batch, 0, is64);
        for (int g = 0; g <= b0; g++) g_gstart[g] = 0;
    } else {
        int bp = load_idx(batch, i - 1, is64);
        if (i == NN) {
            for (int g = bp + 1; g <= GG; g++) g_gstart[g] = NN;
        } else {
            int b = load_idx(batch, i, is64);
            if (b != bp)
                for (int g = bp + 1; g <= b; g++) g_gstart[g] = i;
        }
    }
}

// ---------------- degree histogram ----------------
__global__ void k_deg(const void* edge) {
    int i = blockIdx.x * blockDim.x + threadIdx.x;
    if (i >= EP) return;
    int d;
    if (i < EE) d = load_idx(edge, (long long)EE + i, g_is64);
    else        d = i - EE;
    atomicAdd(&g_deg[d], 1);
}

// ---------------- multi-block exclusive scan ----------------
__global__ void __launch_bounds__(1024) k_scanA() {
    __shared__ int wsum[32];
    int i = blockIdx.x * 1024 + threadIdx.x;
    int lane = threadIdx.x & 31, wid = threadIdx.x >> 5;
    int v = (i < NN) ? g_deg[i] : 0;
    int inc = v;
#pragma unroll
    for (int o = 1; o < 32; o <<= 1) {
        int t = __shfl_up_sync(0xFFFFFFFFu, inc, o);
        if (lane >= o) inc += t;
    }
    if (lane == 31) wsum[wid] = inc;
    __syncthreads();
    if (wid == 0) {
        int wv = wsum[lane];
        int winc = wv;
#pragma unroll
        for (int o = 1; o < 32; o <<= 1) {
            int t = __shfl_up_sync(0xFFFFFFFFu, winc, o);
            if (lane >= o) winc += t;
        }
        wsum[lane] = winc - wv;
        if (lane == 31) g_bsum[blockIdx.x] = winc;
    }
    __syncthreads();
    int ex = inc - v + wsum[wid];
    if (i < NN) g_ptr[i] = ex;
}

__global__ void k_scanB() {
    __shared__ int s[64];
    int t = threadIdx.x;
    int v = (t < NB) ? g_bsum[t] : 0;
    s[t] = v;
    __syncthreads();
    for (int o = 1; o < 64; o <<= 1) {
        int x = (t >= o) ? s[t - o] : 0;
        __syncthreads();
        s[t] += x;
        __syncthreads();
    }
    if (t < NB) g_boff[t] = s[t] - v;
    if (t == 63) g_ptr[NN] = s[63];
}

__global__ void __launch_bounds__(1024) k_scanC() {
    int i = blockIdx.x * 1024 + threadIdx.x;
    if (i >= NN) return;
    g_ptr[i] += g_boff[i >> 10];
    g_fill[i] = 0;
}

// ---------------- scatter into CSR ----------------
__global__ void k_scatter(const void* edge) {
    int i = blockIdx.x * blockDim.x + threadIdx.x;
    if (i >= EP) return;
    int s, d;
    if (i < EE) {
        int is64 = g_is64;
        s = load_idx(edge, i, is64);
        d = load_idx(edge, (long long)EE + i, is64);
    } else {
        s = i - EE; d = s;
    }
    int pos = atomicAdd(&g_fill[d], 1);
    g_col[g_ptr[d] + pos] = s;
}

// ---------------- tf32 tensor-core GEMM + fused alpha ---------------------
#define AS_STRIDE 36
#define BS_STRIDE 136
__global__ void __launch_bounds__(256) k_gemm(const float* __restrict__ A,
                                              const float* __restrict__ W,
                                              const float* __restrict__ a_src,
                                              const float* __restrict__ a_dst,
                                              int use_x) {
    __shared__ unsigned As[128 * AS_STRIDE];
    __shared__ unsigned Bs[32 * BS_STRIDE];
    __shared__ float s_as[128][2];
    __shared__ float s_ad[128][2];

    const float* Ap = use_x ? A : (const float*)g_in;
    int row0 = blockIdx.x * 128;
    int tid = threadIdx.x;
    int wid = tid >> 5, lane = tid & 31;
    int g = lane >> 2, t = lane & 3;
    int wr = wid >> 2, wc = wid & 3;
    int head = wc >> 1;

    if (tid < 128) { s_as[tid][0] = 0.f; s_as[tid][1] = 0.f;
                     s_ad[tid][0] = 0.f; s_ad[tid][1] = 0.f; }

    float acc[4][4][4];
#pragma unroll
    for (int mf = 0; mf < 4; mf++)
#pragma unroll
        for (int nf = 0; nf < 4; nf++)
#pragma unroll
            for (int c = 0; c < 4; c++) acc[mf][nf][c] = 0.f;

    for (int k0 = 0; k0 < 128; k0 += 32) {
#pragma unroll
        for (int l = 0; l < 4; l++) {
            int idx = tid + l * 256;
            int row = idx >> 3;
            int k4 = (idx & 7) << 2;
            int grow = row0 + row;
            float4 v = (grow < NN) ? *(const float4*)&Ap[grow * HC + k0 + k4]
                                   : make_float4(0.f, 0.f, 0.f, 0.f);
            unsigned* p = &As[row * AS_STRIDE + k4];
            p[0] = f2tf32(v.x); p[1] = f2tf32(v.y);
            p[2] = f2tf32(v.z); p[3] = f2tf32(v.w);
        }
#pragma unroll
        for (int l = 0; l < 4; l++) {
            int idx = tid + l * 256;
            int k = idx >> 5;
            int n4 = (idx & 31) << 2;
            float4 v = *(const float4*)&W[(k0 + k) * HC + n4];
            unsigned* p = &Bs[k * BS_STRIDE + n4];
            p[0] = f2tf32(v.x); p[1] = f2tf32(v.y);
            p[2] = f2tf32(v.z); p[3] = f2tf32(v.w);
        }
        __syncthreads();

#pragma unroll
        for (int kk = 0; kk < 32; kk += 8) {
            unsigned af[4][4];
#pragma unroll
            for (int mf = 0; mf < 4; mf++) {
                int r = wr * 64 + mf * 16 + g;
                af[mf][0] = As[r * AS_STRIDE + kk + t];
                af[mf][1] = As[(r + 8) * AS_STRIDE + kk + t];
                af[mf][2] = As[r * AS_STRIDE + kk + t + 4];
                af[mf][3] = As[(r + 8) * AS_STRIDE + kk + t + 4];
            }
            unsigned bf[4][2];
#pragma unroll
            for (int nf = 0; nf < 4; nf++) {
                int n = wc * 32 + nf * 8 + g;
                bf[nf][0] = Bs[(kk + t) * BS_STRIDE + n];
                bf[nf][1] = Bs[(kk + t + 4) * BS_STRIDE + n];
            }
#pragma unroll
            for (int mf = 0; mf < 4; mf++)
#pragma unroll
                for (int nf = 0; nf < 4; nf++)
                    mma_tf32(acc[mf][nf], af[mf], bf[nf]);
        }
        __syncthreads();
    }

    float asv[8], adv[8];
#pragma unroll
    for (int nf = 0; nf < 4; nf++) {
#pragma unroll
        for (int c = 0; c < 2; c++) {
            int col = wc * 32 + nf * 8 + 2 * t + c;
            asv[nf * 2 + c] = a_src[col];
            adv[nf * 2 + c] = a_dst[col];
        }
    }

#pragma unroll
    for (int mf = 0; mf < 4; mf++) {
#pragma unroll
        for (int r = 0; r < 2; r++) {
            int rloc = wr * 64 + mf * 16 + g + 8 * r;
            int grow = row0 + rloc;
            float ps = 0.f, pd = 0.f;
#pragma unroll
            for (int nf = 0; nf < 4; nf++) {
                float v0 = acc[mf][nf][2 * r];
                float v1 = acc[mf][nf][2 * r + 1];
                ps += v0 * asv[nf * 2] + v1 * asv[nf * 2 + 1];
                pd += v0 * adv[nf * 2] + v1 * adv[nf * 2 + 1];
                if (grow < NN) {
                    int col = wc * 32 + nf * 8 + 2 * t;
                    *(__nv_bfloat162*)&g_hb[grow * HC + col] =
                        __floats2bfloat162_rn(v0, v1);
                }
            }
            ps += __shfl_xor_sync(0xFFFFFFFFu, ps, 1);
            ps += __shfl_xor_sync(0xFFFFFFFFu, ps, 2);
            pd += __shfl_xor_sync(0xFFFFFFFFu, pd, 1);
            pd += __shfl_xor_sync(0xFFFFFFFFu, pd, 2);
            if (t == 0) {
                atomicAdd(&s_as[rloc][head], ps);
                atomicAdd(&s_ad[rloc][head], pd);
            }
        }
    }
    __syncthreads();

    if (tid < 128) {
        int grow = row0 + tid;
        if (grow < NN) {
            *(float2*)&g_as[grow * 2] = make_float2(s_as[tid][0], s_as[tid][1]);
            *(float2*)&g_ad[grow * 2] = make_float2(s_ad[tid][0], s_ad[tid][1]);
        }
    }
}

// ---------------- fused softmax + aggregation: warp per dst node ---------
__global__ void __launch_bounds__(256) k_node(const float* __restrict__ b) {
    __shared__ int    sh_s[8][32];
    __shared__ float2 sh_a[8][32];
    int w = (blockIdx.x * blockDim.x + threadIdx.x) >> 5;
    if (w >= NN) return;
    int lane = threadIdx.x & 31;
    int wl = (threadIdx.x >> 5);
    int beg = g_ptr[w], end = g_ptr[w + 1];
    int deg = end - beg;
    float2 ad = *(const float2*)&g_ad[w * 2];

    int f = lane * 4;
    int head = f >> 6;
    float4 acc = make_float4(0.f, 0.f, 0.f, 0.f);

    if (deg <= 32) {
        int s = 0;
        float e0 = -INFINITY, e1 = -INFINITY;
        if (lane < deg) {
            s = g_col[beg + lane];
            float2 as = *(const float2*)&g_as[s * 2];
            e0 = lrelu(as.x + ad.x);
            e1 = lrelu(as.y + ad.y);
        }
        float m0 = e0, m1 = e1;
#pragma unroll
        for (int o = 16; o; o >>= 1) {
            m0 = fmaxf(m0, __shfl_xor_sync(0xFFFFFFFFu, m0, o));
            m1 = fmaxf(m1, __shfl_xor_sync(0xFFFFFFFFu, m1, o));
        }
        float x0 = (lane < deg) ? __expf(e0 - m0) : 0.f;
        float x1 = (lane < deg) ? __expf(e1 - m1) : 0.f;
        float s0 = x0, s1 = x1;
#pragma unroll
        for (int o = 16; o; o >>= 1) {
            s0 += __shfl_xor_sync(0xFFFFFFFFu, s0, o);
            s1 += __shfl_xor_sync(0xFFFFFFFFu, s1, o);
        }
        sh_s[wl][lane] = s;
        sh_a[wl][lane] = make_float2(x0 / (s0 + 1e-16f), x1 / (s1 + 1e-16f));
        __syncwarp();

        int j = 0;
        for (; j + 3 < deg; j += 4) {
            int    i0 = sh_s[wl][j],     i1 = sh_s[wl][j + 1];
            int    i2 = sh_s[wl][j + 2], i3 = sh_s[wl][j + 3];
            float2 w0 = sh_a[wl][j],     w1 = sh_a[wl][j + 1];
            float2 w2 = sh_a[wl][j + 2], w3 = sh_a[wl][j + 3];
            float a0 = head ? w0.y : w0.x;
            float a1 = head ? w1.y : w1.x;
            float a2 = head ? w2.y : w2.x;
            float a3 = head ? w3.y : w3.x;
            acc_bf16(acc, a0, &g_hb[i0 * HC + f]);
            acc_bf16(acc, a1, &g_hb[i1 * HC + f]);
            acc_bf16(acc, a2, &g_hb[i2 * HC + f]);
            acc_bf16(acc, a3, &g_hb[i3 * HC + f]);
        }
        for (; j < deg; j++) {
            int    sj = sh_s[wl][j];
            float2 wj = sh_a[wl][j];
            float  aj = head ? wj.y : wj.x;
            acc_bf16(acc, aj, &g_hb[sj * HC + f]);
        }
    } else {
        float m0 = -INFINITY, m1 = -INFINITY;
        for (int j = beg + lane; j < end; j += 32) {
            int s = g_col[j];
            float2 as = *(const float2*)&g_as[s * 2];
            float e0 = lrelu(as.x + ad.x);
            float e1 = lrelu(as.y + ad.y);
            *(float2*)&g_e[j * 2] = make_float2(e0, e1);
            m0 = fmaxf(m0, e0); m1 = fmaxf(m1, e1);
        }
#pragma unroll
        for (int o = 16; o; o >>= 1) {
            m0 = fmaxf(m0, __shfl_xor_sync(0xFFFFFFFFu, m0, o));
            m1 = fmaxf(m1, __shfl_xor_sync(0xFFFFFFFFu, m1, o));
        }
        float s0 = 0.f, s1 = 0.f;
        for (int j = beg + lane; j < end; j += 32) {
            float2 e = *(const float2*)&g_e[j * 2];
            float x0 = __expf(e.x - m0);
            float x1 = __expf(e.y - m1);
            *(float2*)&g_e[j * 2] = make_float2(x0, x1);
            s0 += x0; s1 += x1;
        }
#pragma unroll
        for (int o = 16; o; o >>= 1) {
            s0 += __shfl_xor_sync(0xFFFFFFFFu, s0, o);
            s1 += __shfl_xor_sync(0xFFFFFFFFu, s1, o);
        }
        float inv = head ? 1.f / (s1 + 1e-16f) : 1.f / (s0 + 1e-16f);
        __syncwarp();
        for (int j = beg; j < end; j++) {
            int s = g_col[j];
            float a = g_e[j * 2 + head] * inv;
            acc_bf16(acc, a, &g_hb[s * HC + f]);
        }
    }

    float4 bb = *(const float4*)&b[f];
    acc.x = fmaxf(acc.x + bb.x, 0.f);
    acc.y = fmaxf(acc.y + bb.y, 0.f);
    acc.z = fmaxf(acc.z + bb.z, 0.f);
    acc.w = fmaxf(acc.w + bb.w, 0.f);
    *(float4*)&g_in[w * HC + f] = acc;
}

// ---------------- fused pool + MLP head ----------------
__global__ void __launch_bounds__(256) k_head(
        const float* __restrict__ w1, const float* __restrict__ b1,
        const float* __restrict__ w2, const float* __restrict__ b2,
        const float* __restrict__ w3, const float* __restrict__ b3,
        float* __restrict__ out) {
    __shared__ float pool[HC];
    __shared__ float r1[L1S];
    __shared__ float r2[L2S];
    int g = blockIdx.x, tid = threadIdx.x;
    int beg = g_gstart[g], end = g_gstart[g + 1];

    if (tid < HC) {
        float sum = 0.f;
        for (int n = beg; n < end; n++) sum += g_in[n * HC + tid];
        pool[tid] = sum / fmaxf((float)(end - beg), 1.f);
    }
    __syncthreads();

    {
        float acc = 0.f;
#pragma unroll 4
        for (int k = 0; k < HC; k++) acc += pool[k] * w1[k * L1S + tid];
        acc += b1[tid];
        r1[tid] = acc > 0.f ? acc : 0.f;
    }
    __syncthreads();

    if (tid < L2S) {
        float acc = 0.f;
#pragma unroll 4
        for (int k = 0; k < L1S; k++) acc += r1[k] * w2[k * L2S + tid];
        acc += b2[tid];
        r2[tid] = acc > 0.f ? acc : 0.f;
    }
    __syncthreads();

    if (tid < OUTS) {
        float acc = 0.f;
#pragma unroll 4
        for (int k = 0; k < L2S; k++) acc += r2[k] * w3[k * OUTS + tid];
        out[g * OUTS + tid] = acc + b3[tid];
    }
}

// ---------------- host orchestration ----------------
extern "C" void kernel_launch(void* const* d_in, const int* in_sizes, int n_in,
                              void* d_out, int out_size) {
    const float* x       = (const float*)d_in[0];
    const void*  edge    = d_in[1];
    const void*  batch   = d_in[2];
    const float* W[3]    = {(const float*)d_in[3], (const float*)d_in[7],  (const float*)d_in[11]};
    const float* asrc[3] = {(const float*)d_in[4], (const float*)d_in[8],  (const float*)d_in[12]};
    const float* adst[3] = {(const float*)d_in[5], (const float*)d_in[9],  (const float*)d_in[13]};
    const float* bias[3] = {(const float*)d_in[6], (const float*)d_in[10], (const float*)d_in[14]};
    const float* lin1_w = (const float*)d_in[15];
    const float* lin1_b = (const float*)d_in[16];
    const float* lin2_w = (const float*)d_in[17];
    const float* lin2_b = (const float*)d_in[18];
    const float* out_w  = (const float*)d_in[19];
    const float* out_b  = (const float*)d_in[20];
    float* out = (float*)d_out;

    const int edge_blocks  = (EP + 255) / 256;
    const int gemm_blocks  = (NN + 127) / 128;
    const int warp8_blocks = (NN + 7) / 8;

    k_detect<<<1, 256>>>(edge);
    k_prep<<<(NN + 256) / 256, 256>>>(batch);
    k_deg<<<edge_blocks, 256>>>(edge);
    k_scanA<<<NB, 1024>>>();
    k_scanB<<<1, 64>>>();
    k_scanC<<<NB, 1024>>>();
    k_scatter<<<edge_blocks, 256>>>(edge);

    for (int l = 0; l < 3; l++) {
        k_gemm<<<gemm_blocks, 256>>>(x, W[l], asrc[l], adst[l], l == 0 ? 1 : 0);
        k_node<<<warp8_blocks, 256>>>(bias[l]);
    }

    k_head<<<GG, 256>>>(lin1_w, lin1_b, lin2_w, lin2_b, out_w, out_b, out);
}